// round 1
// baseline (speedup 1.0000x reference)
#include <cuda_runtime.h>
#include <cuda_bf16.h>
#include <math.h>

// Problem constants
#define BB 8
#define NN_ 2048
#define DD 256
#define HH 256
#define ROWS (BB*NN_)          // 16384
#define ALPHA 0.2f

// ---------------- scratch (device globals; no cudaMalloc allowed) ----------
__device__ float g_Wh [ROWS*HH];       // 16.8 MB
__device__ float g_go [ROWS*HH];       // 16.8 MB
__device__ float g_gi [ROWS*3*HH];     // 50.3 MB
__device__ float g_gh [ROWS*3*HH];     // 50.3 MB
__device__ float g_Wh1[ROWS];
__device__ float g_Wh2[ROWS];
__device__ float g_rm [ROWS];
__device__ float g_rs [ROWS];

// ---------------- tiled fp32 SGEMM: C[M,N] = A[M,K] @ op(B) (+ bias) -------
// BT=false: B is K x N (row-major).  BT=true: B is N x K (row-major), use B^T.
#define BM 128
#define BN 128
#define BK 16
#define TM 8
#define TN 8

template<bool BT, bool HAS_BIAS>
__global__ __launch_bounds__(256)
void sgemm_kernel(const float* __restrict__ A, const float* __restrict__ Bm,
                  const float* __restrict__ bias, float* __restrict__ C,
                  int M, int N, int K)
{
    __shared__ float As[BK][BM];
    __shared__ float Bs[BK][BN];

    const int tid = threadIdx.x;
    const int m0 = blockIdx.y * BM;
    const int n0 = blockIdx.x * BN;
    const int tx = tid & 15;
    const int ty = tid >> 4;

    float acc[TM][TN];
#pragma unroll
    for (int i = 0; i < TM; i++)
#pragma unroll
        for (int j = 0; j < TN; j++) acc[i][j] = 0.f;

    for (int k0 = 0; k0 < K; k0 += BK) {
        // ---- load A tile (BM x BK), store transposed As[k][m]
#pragma unroll
        for (int s = 0; s < 2; s++) {
            int f4 = tid + 256 * s;       // 512 float4 total
            int row = f4 >> 2;            // 0..127
            int c4  = f4 & 3;             // 0..3
            float4 v = *(const float4*)(A + (size_t)(m0 + row) * K + k0 + c4 * 4);
            As[c4*4+0][row] = v.x;
            As[c4*4+1][row] = v.y;
            As[c4*4+2][row] = v.z;
            As[c4*4+3][row] = v.w;
        }
        // ---- load B tile -> Bs[k][n]
        if (BT) {
            // B: N x K row-major; tile rows n0..n0+127, cols k0..k0+15
#pragma unroll
            for (int s = 0; s < 2; s++) {
                int f4 = tid + 256 * s;
                int row = f4 >> 2;        // n index 0..127
                int c4  = f4 & 3;         // k group
                float4 v = *(const float4*)(Bm + (size_t)(n0 + row) * K + k0 + c4 * 4);
                Bs[c4*4+0][row] = v.x;
                Bs[c4*4+1][row] = v.y;
                Bs[c4*4+2][row] = v.z;
                Bs[c4*4+3][row] = v.w;
            }
        } else {
            // B: K x N row-major; tile rows k0..k0+15, cols n0..n0+127
#pragma unroll
            for (int s = 0; s < 2; s++) {
                int f4 = tid + 256 * s;   // 512 float4 = 16 rows * 32 f4
                int row = f4 >> 5;        // 0..15
                int c4  = f4 & 31;        // 0..31
                float4 v = *(const float4*)(Bm + (size_t)(k0 + row) * N + n0 + c4 * 4);
                *(float4*)&Bs[row][c4*4] = v;
            }
        }
        __syncthreads();

#pragma unroll
        for (int kk = 0; kk < BK; kk++) {
            float af[TM], bf[TN];
#pragma unroll
            for (int i = 0; i < TM; i++) af[i] = As[kk][ty*TM + i];
#pragma unroll
            for (int j = 0; j < TN; j++) bf[j] = Bs[kk][tx*TN + j];
#pragma unroll
            for (int i = 0; i < TM; i++)
#pragma unroll
                for (int j = 0; j < TN; j++)
                    acc[i][j] += af[i] * bf[j];
        }
        __syncthreads();
    }

    // ---- epilogue
#pragma unroll
    for (int i = 0; i < TM; i++) {
        int m = m0 + ty*TM + i;
        float* cp = C + (size_t)m * N + n0 + tx*TN;
#pragma unroll
        for (int j = 0; j < TN; j += 4) {
            float4 v;
            v.x = acc[i][j+0]; v.y = acc[i][j+1]; v.z = acc[i][j+2]; v.w = acc[i][j+3];
            if (HAS_BIAS) {
                int n = n0 + tx*TN + j;
                v.x += bias[n+0]; v.y += bias[n+1]; v.z += bias[n+2]; v.w += bias[n+3];
            }
            *(float4*)(cp + j) = v;
        }
    }
}

// ---------------- Wh1/Wh2 : per-row dot with a[:H] and a[H:] ---------------
__global__ __launch_bounds__(256)
void wh12_kernel(const float* __restrict__ Wh, const float* __restrict__ a,
                 float* __restrict__ Wh1, float* __restrict__ Wh2)
{
    int warp = threadIdx.x >> 5;
    int lane = threadIdx.x & 31;
    int row = blockIdx.x * 8 + warp;          // < 16384
    const float* wr = Wh + (size_t)row * HH;
    float s1 = 0.f, s2 = 0.f;
#pragma unroll
    for (int s = 0; s < 8; s++) {
        int h = lane + 32 * s;
        float v = wr[h];
        s1 += v * a[h];
        s2 += v * a[HH + h];
    }
#pragma unroll
    for (int o = 16; o; o >>= 1) {
        s1 += __shfl_xor_sync(0xffffffffu, s1, o);
        s2 += __shfl_xor_sync(0xffffffffu, s2, o);
    }
    if (lane == 0) { Wh1[row] = s1; Wh2[row] = s2; }
}

// ---------------- masked-softmax row stats (max + denom) -------------------
__global__ __launch_bounds__(256)
void row_stats_kernel(const float* __restrict__ Wh1, const float* __restrict__ Wh2,
                      const int* __restrict__ adj,
                      float* __restrict__ rmax, float* __restrict__ rsum)
{
    int r = blockIdx.x;                 // 0..16383  (b*N + i)
    int b = r >> 11;
    const int* arow = adj + (size_t)r * NN_;
    const float* Wh2b = Wh2 + (b << 11);
    float w1 = Wh1[r];
    int tid = threadIdx.x;

    float lrv[8];
    float mx = -INFINITY;
#pragma unroll
    for (int s = 0; s < 8; s++) {
        int j = tid + (s << 8);
        float sv = w1 + Wh2b[j];
        float lr = sv > 0.f ? sv : ALPHA * sv;
        lrv[s] = (arow[j] > 0) ? lr : -INFINITY;
        mx = fmaxf(mx, lrv[s]);
    }

    __shared__ float sred[8];
#pragma unroll
    for (int o = 16; o; o >>= 1) mx = fmaxf(mx, __shfl_xor_sync(0xffffffffu, mx, o));
    if ((tid & 31) == 0) sred[tid >> 5] = mx;
    __syncthreads();
    if (tid == 0) {
        float v = sred[0];
#pragma unroll
        for (int w = 1; w < 8; w++) v = fmaxf(v, sred[w]);
        sred[0] = v;
    }
    __syncthreads();
    mx = sred[0];

    float sum = 0.f;
#pragma unroll
    for (int s = 0; s < 8; s++) sum += __expf(lrv[s] - mx);
#pragma unroll
    for (int o = 16; o; o >>= 1) sum += __shfl_xor_sync(0xffffffffu, sum, o);
    __syncthreads();                          // protect sred reuse
    if ((tid & 31) == 0) sred[tid >> 5] = sum;
    __syncthreads();
    if (tid == 0) {
        float v = 0.f;
#pragma unroll
        for (int w = 0; w < 8; w++) v += sred[w];
        rmax[r] = mx;
        rsum[r] = v;
    }
}

// ---------------- fused attention GEMM: go = softmax(mask(e)) @ Wh ---------
// One block: 64 i-rows x full 256 h.  Attention weights recomputed on the fly
// from the rank-1 structure (Wh1[i] + Wh2[j]); never materialized in HBM.
#define AI 64
#define AJ 32
__global__ __launch_bounds__(256)
void attn_gemm_kernel(const float* __restrict__ Wh, const float* __restrict__ Wh1,
                      const float* __restrict__ Wh2, const int* __restrict__ adj,
                      const float* __restrict__ rmax, const float* __restrict__ rsum,
                      float* __restrict__ out)
{
    __shared__ float Whs[AJ][HH];     // 32 KB
    __shared__ float ws [AI][AJ];     // 8 KB
    __shared__ float f1[AI], fm[AI], finv[AI];

    const int b  = blockIdx.y;
    const int i0 = blockIdx.x * AI;
    const int tid = threadIdx.x;

    const float* Wh_b  = Wh  + (size_t)b * NN_ * HH;
    const float* Wh2_b = Wh2 + b * NN_;
    const int*   adj_b = adj + (size_t)b * NN_ * NN_ + (size_t)i0 * NN_;

    if (tid < AI) {
        int r = b * NN_ + i0 + tid;
        f1[tid]   = Wh1[r];
        fm[tid]   = rmax[r];
        finv[tid] = 1.0f / rsum[r];
    }
    __syncthreads();

    const int ty = tid >> 5;      // 0..7  (8 i-rows each)
    const int tx = tid & 31;      // 0..31 (8 h each)

    float acc[8][8];
#pragma unroll
    for (int i = 0; i < 8; i++)
#pragma unroll
        for (int j = 0; j < 8; j++) acc[i][j] = 0.f;

    for (int j0 = 0; j0 < NN_; j0 += AJ) {
        // stage Wh tile [AJ x 256]
#pragma unroll
        for (int s = 0; s < 8; s++) {
            int f4 = tid + 256 * s;       // 2048 float4
            int row = f4 >> 6;
            int c4  = f4 & 63;
            *(float4*)&Whs[row][c4*4] =
                *(const float4*)(Wh_b + (size_t)(j0 + row) * HH + c4 * 4);
        }
        // compute attention weights (unnormalized) for [AI x AJ]
#pragma unroll
        for (int s = 0; s < 8; s++) {
            int idx = tid + 256 * s;      // 2048 = 64*32, jj fastest -> coalesced adj
            int i  = idx >> 5;
            int jj = idx & 31;
            int msk = adj_b[(size_t)i * NN_ + j0 + jj];
            float sv = f1[i] + Wh2_b[j0 + jj];
            float lr = sv > 0.f ? sv : ALPHA * sv;
            ws[i][jj] = (msk > 0) ? __expf(lr - fm[i]) : 0.f;
        }
        __syncthreads();

        // register-tiled micro-GEMM 8i x 8h over 32 j
#pragma unroll
        for (int jj = 0; jj < AJ; jj++) {
            float4 b0 = *(const float4*)&Whs[jj][tx*8];
            float4 b1 = *(const float4*)&Whs[jj][tx*8 + 4];
#pragma unroll
            for (int r2 = 0; r2 < 8; r2++) {
                float w = ws[ty*8 + r2][jj];      // broadcast within warp
                acc[r2][0] += w * b0.x;  acc[r2][1] += w * b0.y;
                acc[r2][2] += w * b0.z;  acc[r2][3] += w * b0.w;
                acc[r2][4] += w * b1.x;  acc[r2][5] += w * b1.y;
                acc[r2][6] += w * b1.z;  acc[r2][7] += w * b1.w;
            }
        }
        __syncthreads();
    }

    // normalize + write
#pragma unroll
    for (int r2 = 0; r2 < 8; r2++) {
        int i = i0 + ty*8 + r2;
        float sc = finv[ty*8 + r2];
        float* op = out + ((size_t)(b * NN_ + i)) * HH + tx*8;
        float4 v0, v1;
        v0.x = acc[r2][0]*sc; v0.y = acc[r2][1]*sc; v0.z = acc[r2][2]*sc; v0.w = acc[r2][3]*sc;
        v1.x = acc[r2][4]*sc; v1.y = acc[r2][5]*sc; v1.z = acc[r2][6]*sc; v1.w = acc[r2][7]*sc;
        *(float4*)op       = v0;
        *(float4*)(op + 4) = v1;
    }
}

// ---------------- GRU elementwise epilogue ---------------------------------
__global__ __launch_bounds__(256)
void gru_final_kernel(const float* __restrict__ gi, const float* __restrict__ gh,
                      const float* __restrict__ x, float* __restrict__ out)
{
    int idx = blockIdx.x * 256 + threadIdx.x;     // < 16384*256
    int row = idx >> 8;
    int c   = idx & 255;
    size_t base = (size_t)row * (3 * HH);
    float ir = gi[base + c],        hr = gh[base + c];
    float iz = gi[base + HH + c],   hz = gh[base + HH + c];
    float in_ = gi[base + 2*HH + c], hn = gh[base + 2*HH + c];
    float rg = 1.f / (1.f + __expf(-(ir + hr)));
    float zg = 1.f / (1.f + __expf(-(iz + hz)));
    float ng = tanhf(in_ + rg * hn);
    out[idx] = (1.f - zg) * ng + zg * x[idx];
}

// ---------------- launch ---------------------------------------------------
extern "C" void kernel_launch(void* const* d_in, const int* in_sizes, int n_in,
                              void* d_out, int out_size)
{
    const int*   adj  = (const int*)  d_in[0];
    const float* x    = (const float*)d_in[1];
    const float* W    = (const float*)d_in[2];
    const float* a    = (const float*)d_in[3];
    const float* w_ih = (const float*)d_in[4];
    const float* w_hh = (const float*)d_in[5];
    const float* b_ih = (const float*)d_in[6];
    const float* b_hh = (const float*)d_in[7];
    float* out = (float*)d_out;

    float *pWh, *pgo, *pgi, *pgh, *pWh1, *pWh2, *prm, *prs;
    cudaGetSymbolAddress((void**)&pWh,  g_Wh);
    cudaGetSymbolAddress((void**)&pgo,  g_go);
    cudaGetSymbolAddress((void**)&pgi,  g_gi);
    cudaGetSymbolAddress((void**)&pgh,  g_gh);
    cudaGetSymbolAddress((void**)&pWh1, g_Wh1);
    cudaGetSymbolAddress((void**)&pWh2, g_Wh2);
    cudaGetSymbolAddress((void**)&prm,  g_rm);
    cudaGetSymbolAddress((void**)&prs,  g_rs);

    // 1) Wh = x @ W                (16384 x 256 x 256, NN)
    dim3 gWh(HH / BN, ROWS / BM);
    sgemm_kernel<false, false><<<gWh, 256>>>(x, W, nullptr, pWh, ROWS, HH, DD);

    // 2) Wh1/Wh2 GEMVs
    wh12_kernel<<<ROWS / 8, 256>>>(pWh, a, pWh1, pWh2);

    // 3) masked softmax row stats
    row_stats_kernel<<<ROWS, 256>>>(pWh1, pWh2, adj, prm, prs);

    // 4) fused attention GEMM -> graph_out
    dim3 ga(NN_ / AI, BB);
    attn_gemm_kernel<<<ga, 256>>>(pWh, pWh1, pWh2, adj, prm, prs, pgo);

    // 5) gi = graph_out @ w_ih^T + b_ih   (16384 x 768 x 256, NT)
    dim3 gG(3 * HH / BN, ROWS / BM);
    sgemm_kernel<true, true><<<gG, 256>>>(pgo, w_ih, b_ih, pgi, ROWS, 3 * HH, DD);

    // 6) gh = x @ w_hh^T + b_hh
    sgemm_kernel<true, true><<<gG, 256>>>(x, w_hh, b_hh, pgh, ROWS, 3 * HH, HH);

    // 7) GRU elementwise
    gru_final_kernel<<<(ROWS * HH) / 256, 256>>>(pgi, pgh, x, out);
}

// round 2
// speedup vs baseline: 2.4168x; 2.4168x over previous
#include <cuda_runtime.h>
#include <cuda_bf16.h>
#include <cstdint>
#include <math.h>

// Problem constants
#define BB 8
#define NN_ 2048
#define DD 256
#define HH 256
#define ROWS (BB*NN_)          // 16384
#define ALPHA 0.2f

// ---------------- scratch (device globals) ---------------------------------
__device__ float    g_Wh [ROWS*HH];       // fp32 Wh (row-major [b*N+i][h])
__device__ uint32_t g_WhT[ROWS*HH];       // tf32 Wh transposed [b][h][i]
__device__ float    g_go [ROWS*HH];
__device__ float    g_gi [ROWS*3*HH];
__device__ float    g_gh [ROWS*3*HH];
__device__ float    g_Wh1[ROWS];
__device__ float    g_Wh2[ROWS];
__device__ float    g_rm [ROWS];
__device__ float    g_rs [ROWS];

// ---------------- tf32 helpers ---------------------------------------------
__device__ __forceinline__ uint32_t f2tf(float f) {
    uint32_t u; asm("cvt.rna.tf32.f32 %0, %1;" : "=r"(u) : "f"(f)); return u;
}
__device__ __forceinline__ void mma_tf32(float* d, const uint32_t* a, const uint32_t* b) {
    asm volatile("mma.sync.aligned.m16n8k8.row.col.f32.tf32.tf32.f32 "
        "{%0,%1,%2,%3}, {%4,%5,%6,%7}, {%8,%9}, {%0,%1,%2,%3};\n"
        : "+f"(d[0]), "+f"(d[1]), "+f"(d[2]), "+f"(d[3])
        : "r"(a[0]), "r"(a[1]), "r"(a[2]), "r"(a[3]), "r"(b[0]), "r"(b[1]));
}

// ---------------- generic tf32 GEMM: C = A @ op(B) (+bias) -----------------
// BT=false: B is K x N row-major.  BT=true: B is N x K row-major (use B^T).
// BM=128, BN=128, BK=32, 256 threads, warp grid 2(m) x 4(n), warp = m64 x n32.
#define GBM 128
#define GBN 128
#define GBK 32
#define AST 36     // [row][k] stride (words): frag LDS bank = (4g+t)%32, conflict-free
#define BST 136    // non-T [k][n] stride: frag LDS bank = (8t+g)%32, conflict-free

template<bool BT, bool HAS_BIAS>
__global__ __launch_bounds__(256, 2)
void tf32_gemm(const float* __restrict__ A, const float* __restrict__ Bm,
               const float* __restrict__ bias, float* __restrict__ C,
               int M, int N, int K)
{
    __shared__ uint32_t As[GBM * AST];   // [m][k]
    __shared__ uint32_t Bs[GBM * AST];   // BT: [n][k] (128*36); non-T: [k][n] (32*136=4352 fits)

    const int tid  = threadIdx.x;
    const int warp = tid >> 5, lane = tid & 31;
    const int g = lane >> 2, t = lane & 3;
    const int wm = warp & 1, wn = warp >> 1;
    const int m0b = blockIdx.y * GBM, n0b = blockIdx.x * GBN;

    float acc[4][4][4] = {};

    for (int k0g = 0; k0g < K; k0g += GBK) {
        // ---- stage A [128 x 32] -> As[m][k]
#pragma unroll
        for (int s = 0; s < 4; s++) {
            int f4 = tid + 256 * s;
            int m = f4 >> 3, k4 = f4 & 7;
            float4 v = *(const float4*)(A + (size_t)(m0b + m) * K + k0g + k4 * 4);
            uint4 u; u.x = f2tf(v.x); u.y = f2tf(v.y); u.z = f2tf(v.z); u.w = f2tf(v.w);
            *(uint4*)&As[m * AST + k4 * 4] = u;
        }
        // ---- stage B
        if (BT) {
#pragma unroll
            for (int s = 0; s < 4; s++) {
                int f4 = tid + 256 * s;
                int n = f4 >> 3, k4 = f4 & 7;
                float4 v = *(const float4*)(Bm + (size_t)(n0b + n) * K + k0g + k4 * 4);
                uint4 u; u.x = f2tf(v.x); u.y = f2tf(v.y); u.z = f2tf(v.z); u.w = f2tf(v.w);
                *(uint4*)&Bs[n * AST + k4 * 4] = u;
            }
        } else {
#pragma unroll
            for (int s = 0; s < 4; s++) {
                int f4 = tid + 256 * s;
                int k = f4 >> 5, n4 = f4 & 31;
                float4 v = *(const float4*)(Bm + (size_t)(k0g + k) * N + n0b + n4 * 4);
                uint4 u; u.x = f2tf(v.x); u.y = f2tf(v.y); u.z = f2tf(v.z); u.w = f2tf(v.w);
                *(uint4*)&Bs[k * BST + n4 * 4] = u;
            }
        }
        __syncthreads();

#pragma unroll
        for (int ks = 0; ks < 4; ks++) {
            const int kk = ks * 8;
            uint32_t af[4][4], bf[4][2];
#pragma unroll
            for (int mf = 0; mf < 4; mf++) {
                int r0 = wm * 64 + mf * 16 + g;
                af[mf][0] = As[(r0    ) * AST + kk + t];
                af[mf][1] = As[(r0 + 8) * AST + kk + t];
                af[mf][2] = As[(r0    ) * AST + kk + t + 4];
                af[mf][3] = As[(r0 + 8) * AST + kk + t + 4];
            }
#pragma unroll
            for (int nf = 0; nf < 4; nf++) {
                int c0 = wn * 32 + nf * 8 + g;
                if (BT) {
                    bf[nf][0] = Bs[c0 * AST + kk + t];
                    bf[nf][1] = Bs[c0 * AST + kk + t + 4];
                } else {
                    bf[nf][0] = Bs[(kk + t    ) * BST + c0];
                    bf[nf][1] = Bs[(kk + t + 4) * BST + c0];
                }
            }
#pragma unroll
            for (int mf = 0; mf < 4; mf++)
#pragma unroll
                for (int nf = 0; nf < 4; nf++)
                    mma_tf32(acc[mf][nf], af[mf], bf[nf]);
        }
        __syncthreads();
    }

    // ---- epilogue
#pragma unroll
    for (int mf = 0; mf < 4; mf++) {
        int row = m0b + wm * 64 + mf * 16 + g;
#pragma unroll
        for (int nf = 0; nf < 4; nf++) {
            int col = n0b + wn * 32 + nf * 8 + 2 * t;
            float b0v = 0.f, b1v = 0.f;
            if (HAS_BIAS) { b0v = bias[col]; b1v = bias[col + 1]; }
            float2 v0 = { acc[mf][nf][0] + b0v, acc[mf][nf][1] + b1v };
            float2 v1 = { acc[mf][nf][2] + b0v, acc[mf][nf][3] + b1v };
            *(float2*)(C + (size_t)row * N + col)       = v0;
            *(float2*)(C + (size_t)(row + 8) * N + col) = v1;
        }
    }
}

// ---------------- transpose + tf32 convert: Wh[b][i][h] -> WhT[b][h][i] ----
__global__ void transpose_cvt(const float* __restrict__ Wh, uint32_t* __restrict__ WhT)
{
    __shared__ float tle[32][33];
    const int b = blockIdx.z;
    const int i0 = blockIdx.x * 32, h0 = blockIdx.y * 32;
    const int tx = threadIdx.x, ty = threadIdx.y;    // 32 x 8
#pragma unroll
    for (int k = 0; k < 4; k++)
        tle[ty + 8 * k][tx] = Wh[(size_t)(b * NN_ + i0 + ty + 8 * k) * HH + h0 + tx];
    __syncthreads();
#pragma unroll
    for (int k = 0; k < 4; k++)
        WhT[(size_t)(b * HH + h0 + ty + 8 * k) * NN_ + i0 + tx] = f2tf(tle[tx][ty + 8 * k]);
}

// ---------------- Wh1/Wh2 GEMVs from WhT (tf32 bits are valid fp32) --------
__global__ __launch_bounds__(256)
void wh12_T(const uint32_t* __restrict__ WhT, const float* __restrict__ a,
            float* __restrict__ Wh1, float* __restrict__ Wh2)
{
    int r = blockIdx.x * 256 + threadIdx.x;   // b*2048 + i
    int b = r >> 11, i = r & (NN_ - 1);
    const uint32_t* base = WhT + (size_t)b * HH * NN_ + i;
    float s1 = 0.f, s2 = 0.f;
#pragma unroll 8
    for (int h = 0; h < HH; h++) {
        float v = __uint_as_float(base[(size_t)h * NN_]);
        s1 += v * a[h];
        s2 += v * a[HH + h];
    }
    Wh1[r] = s1; Wh2[r] = s2;
}

// ---------------- masked-softmax row stats ---------------------------------
__global__ __launch_bounds__(256)
void row_stats_kernel(const float* __restrict__ Wh1, const float* __restrict__ Wh2,
                      const int* __restrict__ adj,
                      float* __restrict__ rmax, float* __restrict__ rsum)
{
    int r = blockIdx.x;
    int b = r >> 11;
    const int* arow = adj + (size_t)r * NN_;
    const float* Wh2b = Wh2 + (b << 11);
    float w1 = Wh1[r];
    int tid = threadIdx.x;

    float lrv[8];
    float mx = -INFINITY;
#pragma unroll
    for (int s = 0; s < 8; s++) {
        int j = tid + (s << 8);
        float sv = w1 + Wh2b[j];
        float lr = sv > 0.f ? sv : ALPHA * sv;
        lrv[s] = (arow[j] > 0) ? lr : -INFINITY;
        mx = fmaxf(mx, lrv[s]);
    }

    __shared__ float sred[8];
#pragma unroll
    for (int o = 16; o; o >>= 1) mx = fmaxf(mx, __shfl_xor_sync(0xffffffffu, mx, o));
    if ((tid & 31) == 0) sred[tid >> 5] = mx;
    __syncthreads();
    if (tid == 0) {
        float v = sred[0];
#pragma unroll
        for (int w = 1; w < 8; w++) v = fmaxf(v, sred[w]);
        sred[0] = v;
    }
    __syncthreads();
    mx = sred[0];

    float sum = 0.f;
#pragma unroll
    for (int s = 0; s < 8; s++) sum += __expf(lrv[s] - mx);
#pragma unroll
    for (int o = 16; o; o >>= 1) sum += __shfl_xor_sync(0xffffffffu, sum, o);
    __syncthreads();
    if ((tid & 31) == 0) sred[tid >> 5] = sum;
    __syncthreads();
    if (tid == 0) {
        float v = 0.f;
#pragma unroll
        for (int w = 0; w < 8; w++) v += sred[w];
        rmax[r] = mx;
        rsum[r] = v;
    }
}

// ---------------- fused attention GEMM on tensor cores ---------------------
// Block: 64 i-rows (n) x 256 h (m), k-loop over j in tiles of 32.
// D[h][i] = sum_j WhT[h][j] * ws[j][i]; epilogue scales by 1/rsum and writes
// out[i][h]. ws never touches HBM.
__global__ __launch_bounds__(256, 2)
void attn_mma(const uint32_t* __restrict__ WhT, const float* __restrict__ Wh1,
              const float* __restrict__ Wh2, const int* __restrict__ adj,
              const float* __restrict__ rmax, const float* __restrict__ rsum,
              float* __restrict__ out)
{
    __shared__ uint32_t WhAs[256 * AST];  // [h][j]  (36864 B)
    __shared__ uint32_t wsBs[64 * AST];   // [i][j]  (9216 B)
    __shared__ float f1s[64], fms[64], fis[64];

    const int b = blockIdx.y, i0 = blockIdx.x * 64;
    const int tid = threadIdx.x;
    const int warp = tid >> 5, lane = tid & 31;
    const int g = lane >> 2, t = lane & 3;
    const int wm = warp >> 1, wn = warp & 1;   // 4 m-warps x 2 n-warps

    const uint32_t* WhT_b = WhT + (size_t)b * HH * NN_;
    const float*    Wh2_b = Wh2 + b * NN_;
    const int*      adj_b = adj + (size_t)b * NN_ * NN_ + (size_t)i0 * NN_;

    if (tid < 64) {
        int r = b * NN_ + i0 + tid;
        f1s[tid] = Wh1[r];
        fms[tid] = rmax[r];
        fis[tid] = 1.0f / rsum[r];
    }
    __syncthreads();

    float acc[4][4][4] = {};

    for (int j0 = 0; j0 < NN_; j0 += 32) {
        // ---- stage WhT tile [256 h x 32 j] (pure copy, already tf32)
#pragma unroll
        for (int s = 0; s < 8; s++) {
            int f4 = tid + 256 * s;
            int h = f4 >> 3, jj4 = f4 & 7;
            uint4 v = *(const uint4*)(WhT_b + (size_t)h * NN_ + j0 + jj4 * 4);
            *(uint4*)&WhAs[h * AST + jj4 * 4] = v;
        }
        // ---- compute attention weights [64 i x 32 j] directly in B layout
#pragma unroll
        for (int s = 0; s < 8; s++) {
            int idx = tid + 256 * s;
            int i = idx >> 5, jj = idx & 31;
            int msk = adj_b[(size_t)i * NN_ + j0 + jj];
            float sv = f1s[i] + Wh2_b[j0 + jj];
            float lr = sv > 0.f ? sv : ALPHA * sv;
            float e = (msk > 0) ? __expf(lr - fms[i]) : 0.f;
            wsBs[i * AST + jj] = f2tf(e);
        }
        __syncthreads();

#pragma unroll
        for (int ks = 0; ks < 4; ks++) {
            const int kk = ks * 8;
            uint32_t af[4][4], bf[4][2];
#pragma unroll
            for (int mf = 0; mf < 4; mf++) {
                int h0 = wm * 64 + mf * 16 + g;
                af[mf][0] = WhAs[(h0    ) * AST + kk + t];
                af[mf][1] = WhAs[(h0 + 8) * AST + kk + t];
                af[mf][2] = WhAs[(h0    ) * AST + kk + t + 4];
                af[mf][3] = WhAs[(h0 + 8) * AST + kk + t + 4];
            }
#pragma unroll
            for (int nf = 0; nf < 4; nf++) {
                int i1 = wn * 32 + nf * 8 + g;
                bf[nf][0] = wsBs[i1 * AST + kk + t];
                bf[nf][1] = wsBs[i1 * AST + kk + t + 4];
            }
#pragma unroll
            for (int mf = 0; mf < 4; mf++)
#pragma unroll
                for (int nf = 0; nf < 4; nf++)
                    mma_tf32(acc[mf][nf], af[mf], bf[nf]);
        }
        __syncthreads();
    }

    // ---- epilogue: D[h][i] -> out[(b*N+i)*H + h] * (1/rsum[i])
#pragma unroll
    for (int mf = 0; mf < 4; mf++) {
        int h = wm * 64 + mf * 16 + g;
#pragma unroll
        for (int nf = 0; nf < 4; nf++) {
            int il = wn * 32 + nf * 8 + 2 * t;
            float s0 = fis[il], s1 = fis[il + 1];
            float* o0 = out + (size_t)(b * NN_ + i0 + il)     * HH;
            float* o1 = out + (size_t)(b * NN_ + i0 + il + 1) * HH;
            o0[h]     = acc[mf][nf][0] * s0;
            o1[h]     = acc[mf][nf][1] * s1;
            o0[h + 8] = acc[mf][nf][2] * s0;
            o1[h + 8] = acc[mf][nf][3] * s1;
        }
    }
}

// ---------------- GRU elementwise epilogue ---------------------------------
__global__ __launch_bounds__(256)
void gru_final_kernel(const float* __restrict__ gi, const float* __restrict__ gh,
                      const float* __restrict__ x, float* __restrict__ out)
{
    int idx = blockIdx.x * 256 + threadIdx.x;
    int row = idx >> 8;
    int c   = idx & 255;
    size_t base = (size_t)row * (3 * HH);
    float ir = gi[base + c],         hr = gh[base + c];
    float iz = gi[base + HH + c],    hz = gh[base + HH + c];
    float in_ = gi[base + 2*HH + c], hn = gh[base + 2*HH + c];
    float rg = 1.f / (1.f + __expf(-(ir + hr)));
    float zg = 1.f / (1.f + __expf(-(iz + hz)));
    float ng = tanhf(in_ + rg * hn);
    out[idx] = (1.f - zg) * ng + zg * x[idx];
}

// ---------------- launch ---------------------------------------------------
extern "C" void kernel_launch(void* const* d_in, const int* in_sizes, int n_in,
                              void* d_out, int out_size)
{
    const int*   adj  = (const int*)  d_in[0];
    const float* x    = (const float*)d_in[1];
    const float* W    = (const float*)d_in[2];
    const float* a    = (const float*)d_in[3];
    const float* w_ih = (const float*)d_in[4];
    const float* w_hh = (const float*)d_in[5];
    const float* b_ih = (const float*)d_in[6];
    const float* b_hh = (const float*)d_in[7];
    float* out = (float*)d_out;

    float *pWh, *pgo, *pgi, *pgh, *pWh1, *pWh2, *prm, *prs;
    uint32_t *pWhT;
    cudaGetSymbolAddress((void**)&pWh,  g_Wh);
    cudaGetSymbolAddress((void**)&pWhT, g_WhT);
    cudaGetSymbolAddress((void**)&pgo,  g_go);
    cudaGetSymbolAddress((void**)&pgi,  g_gi);
    cudaGetSymbolAddress((void**)&pgh,  g_gh);
    cudaGetSymbolAddress((void**)&pWh1, g_Wh1);
    cudaGetSymbolAddress((void**)&pWh2, g_Wh2);
    cudaGetSymbolAddress((void**)&prm,  g_rm);
    cudaGetSymbolAddress((void**)&prs,  g_rs);

    // 1) Wh = x @ W   (tf32 tensor-core GEMM)
    tf32_gemm<false, false><<<dim3(HH / GBN, ROWS / GBM), 256>>>(x, W, nullptr, pWh, ROWS, HH, DD);

    // 2) transpose + tf32-convert Wh -> WhT[b][h][i]
    transpose_cvt<<<dim3(NN_ / 32, HH / 32, BB), dim3(32, 8)>>>(pWh, pWhT);

    // 3) Wh1/Wh2 GEMVs
    wh12_T<<<ROWS / 256, 256>>>(pWhT, a, pWh1, pWh2);

    // 4) masked softmax row stats
    row_stats_kernel<<<ROWS, 256>>>(pWh1, pWh2, adj, prm, prs);

    // 5) fused attention GEMM (tensor cores) -> graph_out
    attn_mma<<<dim3(NN_ / 64, BB), 256>>>(pWhT, pWh1, pWh2, adj, prm, prs, pgo);

    // 6) gi = graph_out @ w_ih^T + b_ih
    tf32_gemm<true, true><<<dim3(3 * HH / GBN, ROWS / GBM), 256>>>(pgo, w_ih, b_ih, pgi, ROWS, 3 * HH, DD);

    // 7) gh = x @ w_hh^T + b_hh
    tf32_gemm<true, true><<<dim3(3 * HH / GBN, ROWS / GBM), 256>>>(x, w_hh, b_hh, pgh, ROWS, 3 * HH, HH);

    // 8) GRU elementwise
    gru_final_kernel<<<(ROWS * HH) / 256, 256>>>(pgi, pgh, x, out);
}

// round 3
// speedup vs baseline: 2.5568x; 1.0579x over previous
#include <cuda_runtime.h>
#include <cuda_bf16.h>
#include <cstdint>
#include <math.h>

// Problem constants
#define BB 8
#define NN_ 2048
#define DD 256
#define HH 256
#define ROWS (BB*NN_)          // 16384
#define ALPHA 0.2f

// ---------------- scratch (device globals) ---------------------------------
__device__ uint32_t g_WhT[ROWS*HH];       // tf32 Wh transposed [b][h][i]
__device__ float    g_go [ROWS*HH];
__device__ float    g_gh [ROWS*3*HH];
__device__ float    g_Wh1[ROWS];
__device__ float    g_Wh2[ROWS];
__device__ float    g_rm [ROWS];
__device__ float    g_rs [ROWS];
__device__ uint8_t  g_bits[(size_t)ROWS*256];   // adjacency bitmask, 256 B/row

// ---------------- tf32 / async helpers -------------------------------------
__device__ __forceinline__ uint32_t f2tf(float f) {
    uint32_t u; asm("cvt.rna.tf32.f32 %0, %1;" : "=r"(u) : "f"(f)); return u;
}
__device__ __forceinline__ void mma_tf32(float* d, const uint32_t* a, const uint32_t* b) {
    asm volatile("mma.sync.aligned.m16n8k8.row.col.f32.tf32.tf32.f32 "
        "{%0,%1,%2,%3}, {%4,%5,%6,%7}, {%8,%9}, {%0,%1,%2,%3};\n"
        : "+f"(d[0]), "+f"(d[1]), "+f"(d[2]), "+f"(d[3])
        : "r"(a[0]), "r"(a[1]), "r"(a[2]), "r"(a[3]), "r"(b[0]), "r"(b[1]));
}
__device__ __forceinline__ void cp16(void* smem, const void* gmem) {
    uint32_t s = (uint32_t)__cvta_generic_to_shared(smem);
    asm volatile("cp.async.cg.shared.global [%0], [%1], 16;\n" :: "r"(s), "l"(gmem));
}
__device__ __forceinline__ void cp_commit() { asm volatile("cp.async.commit_group;\n" ::: "memory"); }
__device__ __forceinline__ void cp_wait0()  { asm volatile("cp.async.wait_group 0;\n" ::: "memory"); }

#define AST 36     // [row][k] word stride: frag LDS bank = (4g+t)%32, conflict-free

// ---------------- GEMM-T: WhT[b][h][i] = (x @ W)^T, tf32 output ------------
// m = h (256), n = global row (16384), k = d. A = W^T (staged transposed),
// B = x rows. BM=128, BN=128, BK=32, 256 threads, warps 2(m) x 4(n).
__global__ __launch_bounds__(256, 2)
void whT_gemm(const float* __restrict__ x, const float* __restrict__ W,
              uint32_t* __restrict__ WhT)
{
    __shared__ uint32_t As[128 * AST];   // [h][d]
    __shared__ uint32_t Bs[128 * AST];   // [i][d]

    const int tid  = threadIdx.x;
    const int warp = tid >> 5, lane = tid & 31;
    const int g = lane >> 2, t = lane & 3;
    const int wm = warp & 1, wn = warp >> 1;
    const int m0 = blockIdx.y * 128;           // h-block (0 or 128)
    const int n0 = blockIdx.x * 128;           // global row block

    float acc[4][4][4] = {};

    for (int k0 = 0; k0 < DD; k0 += 32) {
        // stage A = W^T tile: load W[d][h] coalesced along h, scatter into As[h][d]
#pragma unroll
        for (int s = 0; s < 4; s++) {
            int f4 = tid + 256 * s;            // 1024 = 32 d x 32 h4
            int d = f4 >> 5, h4 = f4 & 31;
            float4 v = *(const float4*)(W + (size_t)(k0 + d) * HH + m0 + h4 * 4);
            As[(h4*4 + 0) * AST + d] = f2tf(v.x);
            As[(h4*4 + 1) * AST + d] = f2tf(v.y);
            As[(h4*4 + 2) * AST + d] = f2tf(v.z);
            As[(h4*4 + 3) * AST + d] = f2tf(v.w);
        }
        // stage B = x rows
#pragma unroll
        for (int s = 0; s < 4; s++) {
            int f4 = tid + 256 * s;
            int n = f4 >> 3, k4 = f4 & 7;
            float4 v = *(const float4*)(x + (size_t)(n0 + n) * DD + k0 + k4 * 4);
            uint4 u; u.x = f2tf(v.x); u.y = f2tf(v.y); u.z = f2tf(v.z); u.w = f2tf(v.w);
            *(uint4*)&Bs[n * AST + k4 * 4] = u;
        }
        __syncthreads();

#pragma unroll
        for (int ks = 0; ks < 4; ks++) {
            const int kk = ks * 8;
            uint32_t af[4][4], bf[4][2];
#pragma unroll
            for (int mf = 0; mf < 4; mf++) {
                int r0 = wm * 64 + mf * 16 + g;
                af[mf][0] = As[(r0    ) * AST + kk + t];
                af[mf][1] = As[(r0 + 8) * AST + kk + t];
                af[mf][2] = As[(r0    ) * AST + kk + t + 4];
                af[mf][3] = As[(r0 + 8) * AST + kk + t + 4];
            }
#pragma unroll
            for (int nf = 0; nf < 4; nf++) {
                int c0 = wn * 32 + nf * 8 + g;
                bf[nf][0] = Bs[c0 * AST + kk + t];
                bf[nf][1] = Bs[c0 * AST + kk + t + 4];
            }
#pragma unroll
            for (int mf = 0; mf < 4; mf++)
#pragma unroll
                for (int nf = 0; nf < 4; nf++)
                    mma_tf32(acc[mf][nf], af[mf], bf[nf]);
        }
        __syncthreads();
    }

    // epilogue: row = h, col = global row index; write transposed, tf32
    const int b  = n0 >> 11;
    const int ib = n0 & (NN_ - 1);
#pragma unroll
    for (int mf = 0; mf < 4; mf++) {
        int h = m0 + wm * 64 + mf * 16 + g;
#pragma unroll
        for (int nf = 0; nf < 4; nf++) {
            int i = ib + wn * 32 + nf * 8 + 2 * t;
            uint2 v0 = { f2tf(acc[mf][nf][0]), f2tf(acc[mf][nf][1]) };
            uint2 v1 = { f2tf(acc[mf][nf][2]), f2tf(acc[mf][nf][3]) };
            *(uint2*)(WhT + (size_t)(b * HH + h)     * NN_ + i) = v0;
            *(uint2*)(WhT + (size_t)(b * HH + h + 8) * NN_ + i) = v1;
        }
    }
}

// ---------------- generic tf32 GEMM (B^T + bias) for gh --------------------
__global__ __launch_bounds__(256, 2)
void tf32_gemm_bt(const float* __restrict__ A, const float* __restrict__ Bm,
                  const float* __restrict__ bias, float* __restrict__ C,
                  int N, int K)
{
    __shared__ uint32_t As[128 * AST];
    __shared__ uint32_t Bs[128 * AST];

    const int tid  = threadIdx.x;
    const int warp = tid >> 5, lane = tid & 31;
    const int g = lane >> 2, t = lane & 3;
    const int wm = warp & 1, wn = warp >> 1;
    const int m0 = blockIdx.y * 128, n0 = blockIdx.x * 128;

    float acc[4][4][4] = {};

    for (int k0 = 0; k0 < K; k0 += 32) {
#pragma unroll
        for (int s = 0; s < 4; s++) {
            int f4 = tid + 256 * s;
            int m = f4 >> 3, k4 = f4 & 7;
            float4 v = *(const float4*)(A + (size_t)(m0 + m) * K + k0 + k4 * 4);
            uint4 u; u.x = f2tf(v.x); u.y = f2tf(v.y); u.z = f2tf(v.z); u.w = f2tf(v.w);
            *(uint4*)&As[m * AST + k4 * 4] = u;
        }
#pragma unroll
        for (int s = 0; s < 4; s++) {
            int f4 = tid + 256 * s;
            int n = f4 >> 3, k4 = f4 & 7;
            float4 v = *(const float4*)(Bm + (size_t)(n0 + n) * K + k0 + k4 * 4);
            uint4 u; u.x = f2tf(v.x); u.y = f2tf(v.y); u.z = f2tf(v.z); u.w = f2tf(v.w);
            *(uint4*)&Bs[n * AST + k4 * 4] = u;
        }
        __syncthreads();

#pragma unroll
        for (int ks = 0; ks < 4; ks++) {
            const int kk = ks * 8;
            uint32_t af[4][4], bf[4][2];
#pragma unroll
            for (int mf = 0; mf < 4; mf++) {
                int r0 = wm * 64 + mf * 16 + g;
                af[mf][0] = As[(r0    ) * AST + kk + t];
                af[mf][1] = As[(r0 + 8) * AST + kk + t];
                af[mf][2] = As[(r0    ) * AST + kk + t + 4];
                af[mf][3] = As[(r0 + 8) * AST + kk + t + 4];
            }
#pragma unroll
            for (int nf = 0; nf < 4; nf++) {
                int c0 = wn * 32 + nf * 8 + g;
                bf[nf][0] = Bs[c0 * AST + kk + t];
                bf[nf][1] = Bs[c0 * AST + kk + t + 4];
            }
#pragma unroll
            for (int mf = 0; mf < 4; mf++)
#pragma unroll
                for (int nf = 0; nf < 4; nf++)
                    mma_tf32(acc[mf][nf], af[mf], bf[nf]);
        }
        __syncthreads();
    }

#pragma unroll
    for (int mf = 0; mf < 4; mf++) {
        int row = m0 + wm * 64 + mf * 16 + g;
#pragma unroll
        for (int nf = 0; nf < 4; nf++) {
            int col = n0 + wn * 32 + nf * 8 + 2 * t;
            float b0v = bias[col], b1v = bias[col + 1];
            float2 v0 = { acc[mf][nf][0] + b0v, acc[mf][nf][1] + b1v };
            float2 v1 = { acc[mf][nf][2] + b0v, acc[mf][nf][3] + b1v };
            *(float2*)(C + (size_t)row * N + col)       = v0;
            *(float2*)(C + (size_t)(row + 8) * N + col) = v1;
        }
    }
}

// ---------------- Wh1/Wh2 GEMVs from WhT -----------------------------------
__global__ __launch_bounds__(256)
void wh12_T(const uint32_t* __restrict__ WhT, const float* __restrict__ a,
            float* __restrict__ Wh1, float* __restrict__ Wh2)
{
    int r = blockIdx.x * 256 + threadIdx.x;
    int b = r >> 11, i = r & (NN_ - 1);
    const uint32_t* base = WhT + (size_t)b * HH * NN_ + i;
    float s1 = 0.f, s2 = 0.f;
#pragma unroll 8
    for (int h = 0; h < HH; h++) {
        float v = __uint_as_float(base[(size_t)h * NN_]);
        s1 += v * a[h];
        s2 += v * a[HH + h];
    }
    Wh1[r] = s1; Wh2[r] = s2;
}

// ---------------- fused: adj pack -> bitmask + masked-softmax stats --------
__global__ __launch_bounds__(256)
void pack_stats(const int* __restrict__ adj, const float* __restrict__ Wh1,
                const float* __restrict__ Wh2, uint8_t* __restrict__ bits,
                float* __restrict__ rmax, float* __restrict__ rsum)
{
    const int r = blockIdx.x;
    const int b = r >> 11;
    const int tid = threadIdx.x;
    const float w1 = Wh1[r];
    const float* Wh2b = Wh2 + (b << 11);

    const int4* ap = (const int4*)(adj + (size_t)r * NN_ + tid * 8);
    int4 a0 = ap[0], a1 = ap[1];
    float4 w0 = *(const float4*)(Wh2b + tid * 8);
    float4 w1v = *(const float4*)(Wh2b + tid * 8 + 4);

    int m[8] = { a0.x > 0, a0.y > 0, a0.z > 0, a0.w > 0,
                 a1.x > 0, a1.y > 0, a1.z > 0, a1.w > 0 };
    float wv[8] = { w0.x, w0.y, w0.z, w0.w, w1v.x, w1v.y, w1v.z, w1v.w };

    unsigned byte = 0;
    float lrv[8];
    float mx = -INFINITY;
#pragma unroll
    for (int k = 0; k < 8; k++) {
        float sv = w1 + wv[k];
        float lr = sv > 0.f ? sv : ALPHA * sv;
        lrv[k] = m[k] ? lr : -INFINITY;
        mx = fmaxf(mx, lrv[k]);
        byte |= (unsigned)m[k] << k;
    }
    bits[(size_t)r * 256 + tid] = (uint8_t)byte;

    __shared__ float sred[8];
#pragma unroll
    for (int o = 16; o; o >>= 1) mx = fmaxf(mx, __shfl_xor_sync(0xffffffffu, mx, o));
    if ((tid & 31) == 0) sred[tid >> 5] = mx;
    __syncthreads();
    if (tid == 0) {
        float v = sred[0];
#pragma unroll
        for (int w = 1; w < 8; w++) v = fmaxf(v, sred[w]);
        sred[0] = v;
    }
    __syncthreads();
    mx = sred[0];

    float sum = 0.f;
#pragma unroll
    for (int k = 0; k < 8; k++) sum += __expf(lrv[k] - mx);
#pragma unroll
    for (int o = 16; o; o >>= 1) sum += __shfl_xor_sync(0xffffffffu, sum, o);
    __syncthreads();
    if ((tid & 31) == 0) sred[tid >> 5] = sum;
    __syncthreads();
    if (tid == 0) {
        float v = 0.f;
#pragma unroll
        for (int w = 0; w < 8; w++) v += sred[w];
        rmax[r] = mx;
        rsum[r] = v;
    }
}

// ---------------- fused attention GEMM (tensor cores, double-buffered) -----
// Block: 64 i (m) x 256 h (n); k-loop over j, 32/tile, 64 tiles.
// A = ws[i][j] (computed in smem from bitmask), B = WhT[h][j] via cp.async.
#define ATTN_SMEM_WORDS (2*256*AST + 2*64*AST + 192)
__global__ __launch_bounds__(256, 2)
void attn_mma(const uint32_t* __restrict__ WhT, const float* __restrict__ Wh1,
              const float* __restrict__ Wh2, const uint8_t* __restrict__ bits,
              const float* __restrict__ rmax, const float* __restrict__ rsum,
              float* __restrict__ out)
{
    extern __shared__ uint32_t dsm[];
    uint32_t* WhA[2] = { dsm, dsm + 256 * AST };
    uint32_t* wsB[2] = { dsm + 2 * 256 * AST, dsm + 2 * 256 * AST + 64 * AST };
    float* f1s = (float*)(dsm + 2 * 256 * AST + 2 * 64 * AST);
    float* fms = f1s + 64;
    float* fis = fms + 64;

    const int b = blockIdx.y, i0 = blockIdx.x * 64;
    const int tid = threadIdx.x;
    const int warp = tid >> 5, lane = tid & 31;
    const int g = lane >> 2, t = lane & 3;
    const int wm = warp >> 2, wn = warp & 3;   // 2 m-warps (i) x 4 n-warps (h)

    const uint32_t* WhT_b = WhT + (size_t)b * HH * NN_;
    const float*    Wh2_b = Wh2 + b * NN_;
    const uint8_t*  bits_b = bits + (size_t)(b * NN_ + i0) * 256;

    if (tid < 64) {
        int r = b * NN_ + i0 + tid;
        f1s[tid] = Wh1[r];
        fms[tid] = rmax[r];
        fis[tid] = 1.0f / rsum[r];
    }
    __syncthreads();

    const int jj = tid & 31;
    const int ibase = tid >> 5;

    // ---- tile staging helpers (inlined via macros for clarity)
    auto issue_wh = [&](int T, int st) {
#pragma unroll
        for (int s = 0; s < 8; s++) {
            int f4 = tid + 256 * s;            // 2048 = 256 h x 8 j4
            int h = f4 >> 3, j4 = f4 & 7;
            cp16(&WhA[st][h * AST + j4 * 4],
                 WhT_b + (size_t)h * NN_ + T * 32 + j4 * 4);
        }
    };
    auto compute_ws = [&](int T, int st) {
        float w2v = Wh2_b[T * 32 + jj];
#pragma unroll
        for (int s = 0; s < 8; s++) {
            int i = ibase + 8 * s;
            uint32_t m32 = *(const uint32_t*)(bits_b + (size_t)i * 256 + T * 4);
            float sv = f1s[i] + w2v;
            float lr = sv > 0.f ? sv : ALPHA * sv;
            float e = ((m32 >> jj) & 1u) ? __expf(lr - fms[i]) : 0.f;
            wsB[st][i * AST + jj] = f2tf(e);
        }
    };

    float acc[2][8][4] = {};

    // prologue
    issue_wh(0, 0); cp_commit();
    compute_ws(0, 0);
    cp_wait0(); __syncthreads();

    for (int T = 0; T < NN_ / 32; T++) {
        const int st = T & 1, nst = st ^ 1;
        if (T + 1 < NN_ / 32) issue_wh(T + 1, nst);
        cp_commit();
        if (T + 1 < NN_ / 32) compute_ws(T + 1, nst);

#pragma unroll
        for (int ks = 0; ks < 4; ks++) {
            const int kk = ks * 8;
            uint32_t af[2][4], bf[8][2];
#pragma unroll
            for (int mf = 0; mf < 2; mf++) {
                int r0 = wm * 32 + mf * 16 + g;
                af[mf][0] = wsB[st][(r0    ) * AST + kk + t];
                af[mf][1] = wsB[st][(r0 + 8) * AST + kk + t];
                af[mf][2] = wsB[st][(r0    ) * AST + kk + t + 4];
                af[mf][3] = wsB[st][(r0 + 8) * AST + kk + t + 4];
            }
#pragma unroll
            for (int nf = 0; nf < 8; nf++) {
                int c0 = wn * 64 + nf * 8 + g;
                bf[nf][0] = WhA[st][c0 * AST + kk + t];
                bf[nf][1] = WhA[st][c0 * AST + kk + t + 4];
            }
#pragma unroll
            for (int mf = 0; mf < 2; mf++)
#pragma unroll
                for (int nf = 0; nf < 8; nf++)
                    mma_tf32(acc[mf][nf], af[mf], bf[nf]);
        }
        cp_wait0(); __syncthreads();
    }

    // epilogue: row=i (coalesced float2 over h)
#pragma unroll
    for (int mf = 0; mf < 2; mf++) {
        int il = wm * 32 + mf * 16 + g;
        float s0 = fis[il], s1 = fis[il + 8];
        float* o0 = out + (size_t)(b * NN_ + i0 + il)     * HH;
        float* o1 = out + (size_t)(b * NN_ + i0 + il + 8) * HH;
#pragma unroll
        for (int nf = 0; nf < 8; nf++) {
            int hc = wn * 64 + nf * 8 + 2 * t;
            float2 v0 = { acc[mf][nf][0] * s0, acc[mf][nf][1] * s0 };
            float2 v1 = { acc[mf][nf][2] * s1, acc[mf][nf][3] * s1 };
            *(float2*)(o0 + hc) = v0;
            *(float2*)(o1 + hc) = v1;
        }
    }
}

// ---------------- fused gi GEMM (3 gates) + GRU epilogue -------------------
// Block: 128 rows x 32 h-cols x 3 gates. gi = go @ w_ih^T + b_ih computed in
// regs; epilogue reads gh triplet + x, applies GRU, writes final out.
__global__ __launch_bounds__(256)
void gru_gemm(const float* __restrict__ go, const float* __restrict__ w_ih,
              const float* __restrict__ b_ih, const float* __restrict__ gh,
              const float* __restrict__ x, float* __restrict__ out)
{
    __shared__ uint32_t As[128 * AST];        // go tile [m][k]
    __shared__ uint32_t Bs[3][32 * AST];      // gate tiles [n][k]

    const int tid  = threadIdx.x;
    const int warp = tid >> 5, lane = tid & 31;
    const int g = lane >> 2, t = lane & 3;
    const int wm = warp >> 1, wn = warp & 1;  // 4 m-warps x 2 n-warps
    const int m0 = blockIdx.y * 128;
    const int h0 = blockIdx.x * 32;

    float acc[3][2][2][4] = {};

    for (int k0 = 0; k0 < HH; k0 += 32) {
#pragma unroll
        for (int s = 0; s < 4; s++) {
            int f4 = tid + 256 * s;
            int m = f4 >> 3, k4 = f4 & 7;
            float4 v = *(const float4*)(go + (size_t)(m0 + m) * HH + k0 + k4 * 4);
            uint4 u; u.x = f2tf(v.x); u.y = f2tf(v.y); u.z = f2tf(v.z); u.w = f2tf(v.w);
            *(uint4*)&As[m * AST + k4 * 4] = u;
        }
        // 3 gate B tiles: 32 n x 32 k each = 256 float4 -> one per thread
#pragma unroll
        for (int gate = 0; gate < 3; gate++) {
            int n = tid >> 3, k4 = tid & 7;
            float4 v = *(const float4*)(w_ih + (size_t)(gate * HH + h0 + n) * HH + k0 + k4 * 4);
            uint4 u; u.x = f2tf(v.x); u.y = f2tf(v.y); u.z = f2tf(v.z); u.w = f2tf(v.w);
            *(uint4*)&Bs[gate][n * AST + k4 * 4] = u;
        }
        __syncthreads();

#pragma unroll
        for (int ks = 0; ks < 4; ks++) {
            const int kk = ks * 8;
            uint32_t af[2][4], bf[3][2][2];
#pragma unroll
            for (int mf = 0; mf < 2; mf++) {
                int r0 = wm * 32 + mf * 16 + g;
                af[mf][0] = As[(r0    ) * AST + kk + t];
                af[mf][1] = As[(r0 + 8) * AST + kk + t];
                af[mf][2] = As[(r0    ) * AST + kk + t + 4];
                af[mf][3] = As[(r0 + 8) * AST + kk + t + 4];
            }
#pragma unroll
            for (int gate = 0; gate < 3; gate++)
#pragma unroll
                for (int nf = 0; nf < 2; nf++) {
                    int c0 = wn * 16 + nf * 8 + g;
                    bf[gate][nf][0] = Bs[gate][c0 * AST + kk + t];
                    bf[gate][nf][1] = Bs[gate][c0 * AST + kk + t + 4];
                }
#pragma unroll
            for (int gate = 0; gate < 3; gate++)
#pragma unroll
                for (int mf = 0; mf < 2; mf++)
#pragma unroll
                    for (int nf = 0; nf < 2; nf++)
                        mma_tf32(acc[gate][mf][nf], af[mf], bf[gate][nf]);
        }
        __syncthreads();
    }

    // ---- GRU epilogue
#pragma unroll
    for (int mf = 0; mf < 2; mf++) {
#pragma unroll
        for (int nf = 0; nf < 2; nf++) {
            int col = h0 + wn * 16 + nf * 8 + 2 * t;
            float br0 = b_ih[col],            br1 = b_ih[col + 1];
            float bz0 = b_ih[HH + col],       bz1 = b_ih[HH + col + 1];
            float bn0 = b_ih[2 * HH + col],   bn1 = b_ih[2 * HH + col + 1];
#pragma unroll
            for (int pr = 0; pr < 2; pr++) {
                int row = m0 + wm * 32 + mf * 16 + g + pr * 8;
                const float* ghr = gh + (size_t)row * (3 * HH);
                float2 hr = *(const float2*)(ghr + col);
                float2 hz = *(const float2*)(ghr + HH + col);
                float2 hn = *(const float2*)(ghr + 2 * HH + col);
                float2 xv = *(const float2*)(x + (size_t)row * HH + col);

                float ir0 = acc[0][mf][nf][pr*2+0] + br0, ir1 = acc[0][mf][nf][pr*2+1] + br1;
                float iz0 = acc[1][mf][nf][pr*2+0] + bz0, iz1 = acc[1][mf][nf][pr*2+1] + bz1;
                float in0 = acc[2][mf][nf][pr*2+0] + bn0, in1 = acc[2][mf][nf][pr*2+1] + bn1;

                float r0g = 1.f / (1.f + __expf(-(ir0 + hr.x)));
                float r1g = 1.f / (1.f + __expf(-(ir1 + hr.y)));
                float z0g = 1.f / (1.f + __expf(-(iz0 + hz.x)));
                float z1g = 1.f / (1.f + __expf(-(iz1 + hz.y)));
                float n0g = tanhf(in0 + r0g * hn.x);
                float n1g = tanhf(in1 + r1g * hn.y);
                float2 o;
                o.x = (1.f - z0g) * n0g + z0g * xv.x;
                o.y = (1.f - z1g) * n1g + z1g * xv.y;
                *(float2*)(out + (size_t)row * HH + col) = o;
            }
        }
    }
}

// ---------------- launch ---------------------------------------------------
extern "C" void kernel_launch(void* const* d_in, const int* in_sizes, int n_in,
                              void* d_out, int out_size)
{
    const int*   adj  = (const int*)  d_in[0];
    const float* x    = (const float*)d_in[1];
    const float* W    = (const float*)d_in[2];
    const float* a    = (const float*)d_in[3];
    const float* w_ih = (const float*)d_in[4];
    const float* w_hh = (const float*)d_in[5];
    const float* b_ih = (const float*)d_in[6];
    const float* b_hh = (const float*)d_in[7];
    float* out = (float*)d_out;

    float *pgo, *pgh, *pWh1, *pWh2, *prm, *prs;
    uint32_t *pWhT; uint8_t *pbits;
    cudaGetSymbolAddress((void**)&pWhT, g_WhT);
    cudaGetSymbolAddress((void**)&pgo,  g_go);
    cudaGetSymbolAddress((void**)&pgh,  g_gh);
    cudaGetSymbolAddress((void**)&pWh1, g_Wh1);
    cudaGetSymbolAddress((void**)&pWh2, g_Wh2);
    cudaGetSymbolAddress((void**)&prm,  g_rm);
    cudaGetSymbolAddress((void**)&prs,  g_rs);
    cudaGetSymbolAddress((void**)&pbits, g_bits);

    cudaFuncSetAttribute(attn_mma, cudaFuncAttributeMaxDynamicSharedMemorySize,
                         ATTN_SMEM_WORDS * 4);

    // 1) WhT = (x @ W)^T  (tf32 out, transposed)
    whT_gemm<<<dim3(ROWS / 128, HH / 128), 256>>>(x, W, pWhT);

    // 2) Wh1/Wh2 GEMVs
    wh12_T<<<ROWS / 256, 256>>>(pWhT, a, pWh1, pWh2);

    // 3) adj -> bitmask + masked softmax stats (single adj pass)
    pack_stats<<<ROWS, 256>>>(adj, pWh1, pWh2, pbits, prm, prs);

    // 4) fused attention GEMM -> graph_out
    attn_mma<<<dim3(NN_ / 64, BB), 256, ATTN_SMEM_WORDS * 4>>>(
        pWhT, pWh1, pWh2, pbits, prm, prs, pgo);

    // 5) gh = x @ w_hh^T + b_hh
    tf32_gemm_bt<<<dim3(3 * HH / 128, ROWS / 128), 256>>>(x, w_hh, b_hh, pgh, 3 * HH, HH);

    // 6) gi GEMM (3 gates) + GRU fused -> out
    gru_gemm<<<dim3(HH / 32, ROWS / 128), 256>>>(pgo, w_ih, b_ih, pgh, x, out);
}

// round 4
// speedup vs baseline: 3.3789x; 1.3215x over previous
#include <cuda_runtime.h>
#include <cuda_fp16.h>
#include <cstdint>
#include <math.h>

// Problem constants
#define BB 8
#define NN_ 2048
#define DD 256
#define HH 256
#define ROWS (BB*NN_)          // 16384
#define ALPHA 0.2f

// ---------------- scratch (device globals) ---------------------------------
__device__ __half   g_WhT[(size_t)ROWS*HH];     // fp16 Wh transposed [b][h][i]
__device__ __half   g_ws [(size_t)ROWS*NN_];    // fp16 attention weights [r][j]
__device__ float    g_go [ROWS*HH];
__device__ float    g_gh [ROWS*3*HH];
__device__ float    g_Wh1[ROWS];
__device__ float    g_Wh2[ROWS];
__device__ float    g_rs [ROWS];

// ---------------- helpers ---------------------------------------------------
__device__ __forceinline__ uint32_t f2tf(float f) {
    uint32_t u; asm("cvt.rna.tf32.f32 %0, %1;" : "=r"(u) : "f"(f)); return u;
}
__device__ __forceinline__ void mma_tf32(float* d, const uint32_t* a, const uint32_t* b) {
    asm volatile("mma.sync.aligned.m16n8k8.row.col.f32.tf32.tf32.f32 "
        "{%0,%1,%2,%3}, {%4,%5,%6,%7}, {%8,%9}, {%0,%1,%2,%3};\n"
        : "+f"(d[0]), "+f"(d[1]), "+f"(d[2]), "+f"(d[3])
        : "r"(a[0]), "r"(a[1]), "r"(a[2]), "r"(a[3]), "r"(b[0]), "r"(b[1]));
}
__device__ __forceinline__ void mma_f16(float* d, const uint32_t* a, const uint32_t* b) {
    asm volatile("mma.sync.aligned.m16n8k16.row.col.f32.f16.f16.f32 "
        "{%0,%1,%2,%3}, {%4,%5,%6,%7}, {%8,%9}, {%0,%1,%2,%3};\n"
        : "+f"(d[0]), "+f"(d[1]), "+f"(d[2]), "+f"(d[3])
        : "r"(a[0]), "r"(a[1]), "r"(a[2]), "r"(a[3]), "r"(b[0]), "r"(b[1]));
}
__device__ __forceinline__ void cp16(void* smem, const void* gmem) {
    uint32_t s = (uint32_t)__cvta_generic_to_shared(smem);
    asm volatile("cp.async.cg.shared.global [%0], [%1], 16;\n" :: "r"(s), "l"(gmem));
}
__device__ __forceinline__ void cp_commit() { asm volatile("cp.async.commit_group;\n" ::: "memory"); }
__device__ __forceinline__ void cp_wait0()  { asm volatile("cp.async.wait_group 0;\n" ::: "memory"); }

#define AST 36     // [row][k] word stride: frag LDS bank = (4g+t)%32, conflict-free

// ---------------- GEMM-T: WhT[b][h][i] = (x @ W)^T, fp16 output ------------
__global__ __launch_bounds__(256, 2)
void whT_gemm(const float* __restrict__ x, const float* __restrict__ W,
              __half* __restrict__ WhT)
{
    __shared__ uint32_t As[128 * AST];   // [h][d]
    __shared__ uint32_t Bs[128 * AST];   // [i][d]

    const int tid  = threadIdx.x;
    const int warp = tid >> 5, lane = tid & 31;
    const int g = lane >> 2, t = lane & 3;
    const int wm = warp & 1, wn = warp >> 1;
    const int m0 = blockIdx.y * 128;           // h-block
    const int n0 = blockIdx.x * 128;           // global row block

    float acc[4][4][4] = {};

    for (int k0 = 0; k0 < DD; k0 += 32) {
#pragma unroll
        for (int s = 0; s < 4; s++) {
            int f4 = tid + 256 * s;
            int d = f4 >> 5, h4 = f4 & 31;
            float4 v = *(const float4*)(W + (size_t)(k0 + d) * HH + m0 + h4 * 4);
            As[(h4*4 + 0) * AST + d] = f2tf(v.x);
            As[(h4*4 + 1) * AST + d] = f2tf(v.y);
            As[(h4*4 + 2) * AST + d] = f2tf(v.z);
            As[(h4*4 + 3) * AST + d] = f2tf(v.w);
        }
#pragma unroll
        for (int s = 0; s < 4; s++) {
            int f4 = tid + 256 * s;
            int n = f4 >> 3, k4 = f4 & 7;
            float4 v = *(const float4*)(x + (size_t)(n0 + n) * DD + k0 + k4 * 4);
            uint4 u; u.x = f2tf(v.x); u.y = f2tf(v.y); u.z = f2tf(v.z); u.w = f2tf(v.w);
            *(uint4*)&Bs[n * AST + k4 * 4] = u;
        }
        __syncthreads();

#pragma unroll
        for (int ks = 0; ks < 4; ks++) {
            const int kk = ks * 8;
            uint32_t af[4][4], bf[4][2];
#pragma unroll
            for (int mf = 0; mf < 4; mf++) {
                int r0 = wm * 64 + mf * 16 + g;
                af[mf][0] = As[(r0    ) * AST + kk + t];
                af[mf][1] = As[(r0 + 8) * AST + kk + t];
                af[mf][2] = As[(r0    ) * AST + kk + t + 4];
                af[mf][3] = As[(r0 + 8) * AST + kk + t + 4];
            }
#pragma unroll
            for (int nf = 0; nf < 4; nf++) {
                int c0 = wn * 32 + nf * 8 + g;
                bf[nf][0] = Bs[c0 * AST + kk + t];
                bf[nf][1] = Bs[c0 * AST + kk + t + 4];
            }
#pragma unroll
            for (int mf = 0; mf < 4; mf++)
#pragma unroll
                for (int nf = 0; nf < 4; nf++)
                    mma_tf32(acc[mf][nf], af[mf], bf[nf]);
        }
        __syncthreads();
    }

    const int b  = n0 >> 11;
    const int ib = n0 & (NN_ - 1);
#pragma unroll
    for (int mf = 0; mf < 4; mf++) {
        int h = m0 + wm * 64 + mf * 16 + g;
#pragma unroll
        for (int nf = 0; nf < 4; nf++) {
            int i = ib + wn * 32 + nf * 8 + 2 * t;
            __half2 v0 = __floats2half2_rn(acc[mf][nf][0], acc[mf][nf][1]);
            __half2 v1 = __floats2half2_rn(acc[mf][nf][2], acc[mf][nf][3]);
            *(__half2*)(WhT + (size_t)(b * HH + h)     * NN_ + i) = v0;
            *(__half2*)(WhT + (size_t)(b * HH + h + 8) * NN_ + i) = v1;
        }
    }
}

// ---------------- generic tf32 GEMM (B^T + bias) for gh --------------------
__global__ __launch_bounds__(256, 2)
void tf32_gemm_bt(const float* __restrict__ A, const float* __restrict__ Bm,
                  const float* __restrict__ bias, float* __restrict__ C,
                  int N, int K)
{
    __shared__ uint32_t As[128 * AST];
    __shared__ uint32_t Bs[128 * AST];

    const int tid  = threadIdx.x;
    const int warp = tid >> 5, lane = tid & 31;
    const int g = lane >> 2, t = lane & 3;
    const int wm = warp & 1, wn = warp >> 1;
    const int m0 = blockIdx.y * 128, n0 = blockIdx.x * 128;

    float acc[4][4][4] = {};

    for (int k0 = 0; k0 < K; k0 += 32) {
#pragma unroll
        for (int s = 0; s < 4; s++) {
            int f4 = tid + 256 * s;
            int m = f4 >> 3, k4 = f4 & 7;
            float4 v = *(const float4*)(A + (size_t)(m0 + m) * K + k0 + k4 * 4);
            uint4 u; u.x = f2tf(v.x); u.y = f2tf(v.y); u.z = f2tf(v.z); u.w = f2tf(v.w);
            *(uint4*)&As[m * AST + k4 * 4] = u;
        }
#pragma unroll
        for (int s = 0; s < 4; s++) {
            int f4 = tid + 256 * s;
            int n = f4 >> 3, k4 = f4 & 7;
            float4 v = *(const float4*)(Bm + (size_t)(n0 + n) * K + k0 + k4 * 4);
            uint4 u; u.x = f2tf(v.x); u.y = f2tf(v.y); u.z = f2tf(v.z); u.w = f2tf(v.w);
            *(uint4*)&Bs[n * AST + k4 * 4] = u;
        }
        __syncthreads();

#pragma unroll
        for (int ks = 0; ks < 4; ks++) {
            const int kk = ks * 8;
            uint32_t af[4][4], bf[4][2];
#pragma unroll
            for (int mf = 0; mf < 4; mf++) {
                int r0 = wm * 64 + mf * 16 + g;
                af[mf][0] = As[(r0    ) * AST + kk + t];
                af[mf][1] = As[(r0 + 8) * AST + kk + t];
                af[mf][2] = As[(r0    ) * AST + kk + t + 4];
                af[mf][3] = As[(r0 + 8) * AST + kk + t + 4];
            }
#pragma unroll
            for (int nf = 0; nf < 4; nf++) {
                int c0 = wn * 32 + nf * 8 + g;
                bf[nf][0] = Bs[c0 * AST + kk + t];
                bf[nf][1] = Bs[c0 * AST + kk + t + 4];
            }
#pragma unroll
            for (int mf = 0; mf < 4; mf++)
#pragma unroll
                for (int nf = 0; nf < 4; nf++)
                    mma_tf32(acc[mf][nf], af[mf], bf[nf]);
        }
        __syncthreads();
    }

#pragma unroll
    for (int mf = 0; mf < 4; mf++) {
        int row = m0 + wm * 64 + mf * 16 + g;
#pragma unroll
        for (int nf = 0; nf < 4; nf++) {
            int col = n0 + wn * 32 + nf * 8 + 2 * t;
            float b0v = bias[col], b1v = bias[col + 1];
            float2 v0 = { acc[mf][nf][0] + b0v, acc[mf][nf][1] + b1v };
            float2 v1 = { acc[mf][nf][2] + b0v, acc[mf][nf][3] + b1v };
            *(float2*)(C + (size_t)row * N + col)       = v0;
            *(float2*)(C + (size_t)(row + 8) * N + col) = v1;
        }
    }
}

// ---------------- Wh1/Wh2 GEMVs from WhT (fp16) ----------------------------
__global__ __launch_bounds__(256)
void wh12_T(const __half* __restrict__ WhT, const float* __restrict__ a,
            float* __restrict__ Wh1, float* __restrict__ Wh2)
{
    int r = blockIdx.x * 256 + threadIdx.x;
    int b = r >> 11, i = r & (NN_ - 1);
    const __half* base = WhT + (size_t)b * HH * NN_ + i;
    float s1 = 0.f, s2 = 0.f;
#pragma unroll 8
    for (int h = 0; h < HH; h++) {
        float v = __half2float(base[(size_t)h * NN_]);
        s1 += v * a[h];
        s2 += v * a[HH + h];
    }
    Wh1[r] = s1; Wh2[r] = s2;
}

// ---------------- fused: adj -> masked softmax stats + fp16 ws matrix ------
__global__ __launch_bounds__(256)
void pack_stats(const int* __restrict__ adj, const float* __restrict__ Wh1,
                const float* __restrict__ Wh2, __half* __restrict__ ws,
                float* __restrict__ rsum)
{
    const int r = blockIdx.x;
    const int b = r >> 11;
    const int tid = threadIdx.x;
    const float w1 = Wh1[r];
    const float* Wh2b = Wh2 + (b << 11);

    const int4* ap = (const int4*)(adj + (size_t)r * NN_ + tid * 8);
    int4 a0 = ap[0], a1 = ap[1];
    float4 w0 = *(const float4*)(Wh2b + tid * 8);
    float4 w1v = *(const float4*)(Wh2b + tid * 8 + 4);

    int m[8] = { a0.x > 0, a0.y > 0, a0.z > 0, a0.w > 0,
                 a1.x > 0, a1.y > 0, a1.z > 0, a1.w > 0 };
    float wv[8] = { w0.x, w0.y, w0.z, w0.w, w1v.x, w1v.y, w1v.z, w1v.w };

    float lrv[8];
    float mx = -INFINITY;
#pragma unroll
    for (int k = 0; k < 8; k++) {
        float sv = w1 + wv[k];
        float lr = sv > 0.f ? sv : ALPHA * sv;
        lrv[k] = m[k] ? lr : -INFINITY;
        mx = fmaxf(mx, lrv[k]);
    }

    __shared__ float sred[8];
#pragma unroll
    for (int o = 16; o; o >>= 1) mx = fmaxf(mx, __shfl_xor_sync(0xffffffffu, mx, o));
    if ((tid & 31) == 0) sred[tid >> 5] = mx;
    __syncthreads();
    if (tid == 0) {
        float v = sred[0];
#pragma unroll
        for (int w = 1; w < 8; w++) v = fmaxf(v, sred[w]);
        sred[0] = v;
    }
    __syncthreads();
    mx = sred[0];

    // exp, accumulate sum, and write fp16 ws
    float ev[8];
    float sum = 0.f;
#pragma unroll
    for (int k = 0; k < 8; k++) { ev[k] = __expf(lrv[k] - mx); sum += ev[k]; }
    __half2 hq[4];
#pragma unroll
    for (int k = 0; k < 4; k++) hq[k] = __floats2half2_rn(ev[2*k], ev[2*k+1]);
    *(uint4*)(ws + (size_t)r * NN_ + tid * 8) = *(uint4*)hq;

#pragma unroll
    for (int o = 16; o; o >>= 1) sum += __shfl_xor_sync(0xffffffffu, sum, o);
    __syncthreads();
    if ((tid & 31) == 0) sred[tid >> 5] = sum;
    __syncthreads();
    if (tid == 0) {
        float v = 0.f;
#pragma unroll
        for (int w = 0; w < 8; w++) v += sred[w];
        rsum[r] = v;
    }
}

// ---------------- attention GEMM: fp16 m16n8k16, pure MMA inner loop -------
// Block: 64 i (m) x 256 h (n); k = j in tiles of 64 (32 iterations).
// A = ws[i][j] (fp16, precomputed), B = WhT[h][j] (fp16). Both via cp.async.
#define ATTN_SMEM_WORDS (2*256*AST + 2*64*AST + 64)
__global__ __launch_bounds__(256, 2)
void attn_mma(const __half* __restrict__ WhT, const __half* __restrict__ ws,
              const float* __restrict__ rsum, float* __restrict__ out)
{
    extern __shared__ uint32_t dsm[];
    uint32_t* WhB[2] = { dsm, dsm + 256 * AST };                    // [h][j-half2]
    uint32_t* wsA[2] = { dsm + 2*256*AST, dsm + 2*256*AST + 64*AST }; // [i][j-half2]
    float* fis = (float*)(dsm + 2*256*AST + 2*64*AST);

    const int b = blockIdx.y, i0 = blockIdx.x * 64;
    const int tid = threadIdx.x;
    const int warp = tid >> 5, lane = tid & 31;
    const int g = lane >> 2, t = lane & 3;
    const int wm = warp >> 2, wn = warp & 3;   // 2 i-warps x 4 h-warps

    const __half* WhT_b = WhT + (size_t)b * HH * NN_;
    const __half* ws_b  = ws  + (size_t)(b * NN_ + i0) * NN_;

    if (tid < 64) fis[tid] = 1.0f / rsum[b * NN_ + i0 + tid];
    __syncthreads();

    auto issue = [&](int T, int st) {
        const __half* wsrc = WhT_b + T * 64;
#pragma unroll
        for (int s = 0; s < 8; s++) {            // 2048 cp16: WhT tile 256h x 64j
            int idx = tid + 256 * s;
            int h = idx >> 3, grp = idx & 7;
            cp16(&WhB[st][h * AST + grp * 4], wsrc + (size_t)h * NN_ + grp * 8);
        }
        const __half* asrc = ws_b + T * 64;
#pragma unroll
        for (int s = 0; s < 2; s++) {            // 512 cp16: ws tile 64i x 64j
            int idx = tid + 256 * s;
            int i = idx >> 3, grp = idx & 7;
            cp16(&wsA[st][i * AST + grp * 4], asrc + (size_t)i * NN_ + grp * 8);
        }
    };

    float acc[2][8][4] = {};

    issue(0, 0); cp_commit(); cp_wait0(); __syncthreads();

    for (int T = 0; T < NN_ / 64; T++) {
        const int st = T & 1, nst = st ^ 1;
        if (T + 1 < NN_ / 64) issue(T + 1, nst);
        cp_commit();

#pragma unroll
        for (int ks = 0; ks < 4; ks++) {
            const int kk = ks * 8;               // half2 offset
            uint32_t af[2][4], bf[8][2];
#pragma unroll
            for (int mf = 0; mf < 2; mf++) {
                int r0 = wm * 32 + mf * 16 + g;
                af[mf][0] = wsA[st][(r0    ) * AST + kk + t];
                af[mf][1] = wsA[st][(r0 + 8) * AST + kk + t];
                af[mf][2] = wsA[st][(r0    ) * AST + kk + t + 4];
                af[mf][3] = wsA[st][(r0 + 8) * AST + kk + t + 4];
            }
#pragma unroll
            for (int nf = 0; nf < 8; nf++) {
                int c0 = wn * 64 + nf * 8 + g;
                bf[nf][0] = WhB[st][c0 * AST + kk + t];
                bf[nf][1] = WhB[st][c0 * AST + kk + t + 4];
            }
#pragma unroll
            for (int mf = 0; mf < 2; mf++)
#pragma unroll
                for (int nf = 0; nf < 8; nf++)
                    mma_f16(acc[mf][nf], af[mf], bf[nf]);
        }
        cp_wait0(); __syncthreads();
    }

    // epilogue: row = i, coalesced float2 over h
#pragma unroll
    for (int mf = 0; mf < 2; mf++) {
        int il = wm * 32 + mf * 16 + g;
        float s0 = fis[il], s1 = fis[il + 8];
        float* o0 = out + (size_t)(b * NN_ + i0 + il)     * HH;
        float* o1 = out + (size_t)(b * NN_ + i0 + il + 8) * HH;
#pragma unroll
        for (int nf = 0; nf < 8; nf++) {
            int hc = wn * 64 + nf * 8 + 2 * t;
            float2 v0 = { acc[mf][nf][0] * s0, acc[mf][nf][1] * s0 };
            float2 v1 = { acc[mf][nf][2] * s1, acc[mf][nf][3] * s1 };
            *(float2*)(o0 + hc) = v0;
            *(float2*)(o1 + hc) = v1;
        }
    }
}

// ---------------- fused gi GEMM (3 gates) + GRU epilogue -------------------
__global__ __launch_bounds__(256)
void gru_gemm(const float* __restrict__ go, const float* __restrict__ w_ih,
              const float* __restrict__ b_ih, const float* __restrict__ gh,
              const float* __restrict__ x, float* __restrict__ out)
{
    __shared__ uint32_t As[128 * AST];
    __shared__ uint32_t Bs[3][32 * AST];

    const int tid  = threadIdx.x;
    const int warp = tid >> 5, lane = tid & 31;
    const int g = lane >> 2, t = lane & 3;
    const int wm = warp >> 1, wn = warp & 1;
    const int m0 = blockIdx.y * 128;
    const int h0 = blockIdx.x * 32;

    float acc[3][2][2][4] = {};

    for (int k0 = 0; k0 < HH; k0 += 32) {
#pragma unroll
        for (int s = 0; s < 4; s++) {
            int f4 = tid + 256 * s;
            int m = f4 >> 3, k4 = f4 & 7;
            float4 v = *(const float4*)(go + (size_t)(m0 + m) * HH + k0 + k4 * 4);
            uint4 u; u.x = f2tf(v.x); u.y = f2tf(v.y); u.z = f2tf(v.z); u.w = f2tf(v.w);
            *(uint4*)&As[m * AST + k4 * 4] = u;
        }
#pragma unroll
        for (int gate = 0; gate < 3; gate++) {
            int n = tid >> 3, k4 = tid & 7;
            float4 v = *(const float4*)(w_ih + (size_t)(gate * HH + h0 + n) * HH + k0 + k4 * 4);
            uint4 u; u.x = f2tf(v.x); u.y = f2tf(v.y); u.z = f2tf(v.z); u.w = f2tf(v.w);
            *(uint4*)&Bs[gate][n * AST + k4 * 4] = u;
        }
        __syncthreads();

#pragma unroll
        for (int ks = 0; ks < 4; ks++) {
            const int kk = ks * 8;
            uint32_t af[2][4], bf[3][2][2];
#pragma unroll
            for (int mf = 0; mf < 2; mf++) {
                int r0 = wm * 32 + mf * 16 + g;
                af[mf][0] = As[(r0    ) * AST + kk + t];
                af[mf][1] = As[(r0 + 8) * AST + kk + t];
                af[mf][2] = As[(r0    ) * AST + kk + t + 4];
                af[mf][3] = As[(r0 + 8) * AST + kk + t + 4];
            }
#pragma unroll
            for (int gate = 0; gate < 3; gate++)
#pragma unroll
                for (int nf = 0; nf < 2; nf++) {
                    int c0 = wn * 16 + nf * 8 + g;
                    bf[gate][nf][0] = Bs[gate][c0 * AST + kk + t];
                    bf[gate][nf][1] = Bs[gate][c0 * AST + kk + t + 4];
                }
#pragma unroll
            for (int gate = 0; gate < 3; gate++)
#pragma unroll
                for (int mf = 0; mf < 2; mf++)
#pragma unroll
                    for (int nf = 0; nf < 2; nf++)
                        mma_tf32(acc[gate][mf][nf], af[mf], bf[gate][nf]);
        }
        __syncthreads();
    }

#pragma unroll
    for (int mf = 0; mf < 2; mf++) {
#pragma unroll
        for (int nf = 0; nf < 2; nf++) {
            int col = h0 + wn * 16 + nf * 8 + 2 * t;
            float br0 = b_ih[col],            br1 = b_ih[col + 1];
            float bz0 = b_ih[HH + col],       bz1 = b_ih[HH + col + 1];
            float bn0 = b_ih[2 * HH + col],   bn1 = b_ih[2 * HH + col + 1];
#pragma unroll
            for (int pr = 0; pr < 2; pr++) {
                int row = m0 + wm * 32 + mf * 16 + g + pr * 8;
                const float* ghr = gh + (size_t)row * (3 * HH);
                float2 hr = *(const float2*)(ghr + col);
                float2 hz = *(const float2*)(ghr + HH + col);
                float2 hn = *(const float2*)(ghr + 2 * HH + col);
                float2 xv = *(const float2*)(x + (size_t)row * HH + col);

                float ir0 = acc[0][mf][nf][pr*2+0] + br0, ir1 = acc[0][mf][nf][pr*2+1] + br1;
                float iz0 = acc[1][mf][nf][pr*2+0] + bz0, iz1 = acc[1][mf][nf][pr*2+1] + bz1;
                float in0 = acc[2][mf][nf][pr*2+0] + bn0, in1 = acc[2][mf][nf][pr*2+1] + bn1;

                float r0g = 1.f / (1.f + __expf(-(ir0 + hr.x)));
                float r1g = 1.f / (1.f + __expf(-(ir1 + hr.y)));
                float z0g = 1.f / (1.f + __expf(-(iz0 + hz.x)));
                float z1g = 1.f / (1.f + __expf(-(iz1 + hz.y)));
                float n0g = tanhf(in0 + r0g * hn.x);
                float n1g = tanhf(in1 + r1g * hn.y);
                float2 o;
                o.x = (1.f - z0g) * n0g + z0g * xv.x;
                o.y = (1.f - z1g) * n1g + z1g * xv.y;
                *(float2*)(out + (size_t)row * HH + col) = o;
            }
        }
    }
}

// ---------------- launch ---------------------------------------------------
extern "C" void kernel_launch(void* const* d_in, const int* in_sizes, int n_in,
                              void* d_out, int out_size)
{
    const int*   adj  = (const int*)  d_in[0];
    const float* x    = (const float*)d_in[1];
    const float* W    = (const float*)d_in[2];
    const float* a    = (const float*)d_in[3];
    const float* w_ih = (const float*)d_in[4];
    const float* w_hh = (const float*)d_in[5];
    const float* b_ih = (const float*)d_in[6];
    const float* b_hh = (const float*)d_in[7];
    float* out = (float*)d_out;

    float *pgo, *pgh, *pWh1, *pWh2, *prs;
    __half *pWhT, *pws;
    cudaGetSymbolAddress((void**)&pWhT, g_WhT);
    cudaGetSymbolAddress((void**)&pws,  g_ws);
    cudaGetSymbolAddress((void**)&pgo,  g_go);
    cudaGetSymbolAddress((void**)&pgh,  g_gh);
    cudaGetSymbolAddress((void**)&pWh1, g_Wh1);
    cudaGetSymbolAddress((void**)&pWh2, g_Wh2);
    cudaGetSymbolAddress((void**)&prs,  g_rs);

    cudaFuncSetAttribute(attn_mma, cudaFuncAttributeMaxDynamicSharedMemorySize,
                         ATTN_SMEM_WORDS * 4);

    // 1) WhT = (x @ W)^T  (fp16 out, transposed)
    whT_gemm<<<dim3(ROWS / 128, HH / 128), 256>>>(x, W, pWhT);

    // 2) Wh1/Wh2 GEMVs
    wh12_T<<<ROWS / 256, 256>>>(pWhT, a, pWh1, pWh2);

    // 3) adj -> softmax stats + fp16 ws matrix (single adj pass)
    pack_stats<<<ROWS, 256>>>(adj, pWh1, pWh2, pws, prs);

    // 4) attention GEMM (fp16 MMA) -> graph_out
    attn_mma<<<dim3(NN_ / 64, BB), 256, ATTN_SMEM_WORDS * 4>>>(pWhT, pws, prs, pgo);

    // 5) gh = x @ w_hh^T + b_hh
    tf32_gemm_bt<<<dim3(3 * HH / 128, ROWS / 128), 256>>>(x, w_hh, b_hh, pgh, 3 * HH, HH);

    // 6) gi GEMM (3 gates) + GRU fused -> out
    gru_gemm<<<dim3(HH / 32, ROWS / 128), 256>>>(pgo, w_ih, b_ih, pgh, x, out);
}

// round 5
// speedup vs baseline: 3.8046x; 1.1260x over previous
#include <cuda_runtime.h>
#include <cuda_fp16.h>
#include <cstdint>
#include <math.h>

// Problem constants
#define BB 8
#define NN_ 2048
#define DD 256
#define HH 256
#define ROWS (BB*NN_)          // 16384
#define ALPHA 0.2f

// ---------------- scratch (device globals) ---------------------------------
__device__ __half   g_WhT [(size_t)ROWS*HH];     // fp16 Wh^T [b][h][i]
__device__ __half   g_ws  [(size_t)ROWS*NN_];    // fp16 attention weights [r][j]
__device__ __half   g_go16[(size_t)ROWS*HH];     // fp16 graph_out
__device__ __half   g_gh16[(size_t)ROWS*3*HH];   // fp16 gh
__device__ __half   g_x16 [(size_t)ROWS*HH];     // fp16 x
__device__ __half   g_wih16[3*HH*HH];
__device__ __half   g_whh16[3*HH*HH];
__device__ float    g_Wh1[ROWS];
__device__ float    g_Wh2[ROWS];
__device__ float    g_rs [ROWS];

// ---------------- helpers ---------------------------------------------------
__device__ __forceinline__ uint32_t f2tf(float f) {
    uint32_t u; asm("cvt.rna.tf32.f32 %0, %1;" : "=r"(u) : "f"(f)); return u;
}
__device__ __forceinline__ void mma_tf32(float* d, const uint32_t* a, const uint32_t* b) {
    asm volatile("mma.sync.aligned.m16n8k8.row.col.f32.tf32.tf32.f32 "
        "{%0,%1,%2,%3}, {%4,%5,%6,%7}, {%8,%9}, {%0,%1,%2,%3};\n"
        : "+f"(d[0]), "+f"(d[1]), "+f"(d[2]), "+f"(d[3])
        : "r"(a[0]), "r"(a[1]), "r"(a[2]), "r"(a[3]), "r"(b[0]), "r"(b[1]));
}
__device__ __forceinline__ void mma_f16(float* d, const uint32_t* a, const uint32_t* b) {
    asm volatile("mma.sync.aligned.m16n8k16.row.col.f32.f16.f16.f32 "
        "{%0,%1,%2,%3}, {%4,%5,%6,%7}, {%8,%9}, {%0,%1,%2,%3};\n"
        : "+f"(d[0]), "+f"(d[1]), "+f"(d[2]), "+f"(d[3])
        : "r"(a[0]), "r"(a[1]), "r"(a[2]), "r"(a[3]), "r"(b[0]), "r"(b[1]));
}
__device__ __forceinline__ void cp16(void* smem, const void* gmem) {
    uint32_t s = (uint32_t)__cvta_generic_to_shared(smem);
    asm volatile("cp.async.cg.shared.global [%0], [%1], 16;\n" :: "r"(s), "l"(gmem));
}
__device__ __forceinline__ void cp_commit() { asm volatile("cp.async.commit_group;\n" ::: "memory"); }
__device__ __forceinline__ void cp_wait0()  { asm volatile("cp.async.wait_group 0;\n" ::: "memory"); }

#define AST 36     // [row][k-word] stride: frag LDS bank = (4g+t)%32, conflict-free

// ---------------- elementwise fp32 -> fp16 converters ----------------------
__global__ __launch_bounds__(256)
void cvt_f16(const float* __restrict__ src, __half* __restrict__ dst)
{
    int i = (blockIdx.x * 256 + threadIdx.x) * 8;
    float4 v0 = *(const float4*)(src + i);
    float4 v1 = *(const float4*)(src + i + 4);
    __half2 h[4] = { __floats2half2_rn(v0.x, v0.y), __floats2half2_rn(v0.z, v0.w),
                     __floats2half2_rn(v1.x, v1.y), __floats2half2_rn(v1.z, v1.w) };
    *(uint4*)(dst + i) = *(uint4*)h;
}

// ---------------- GEMM-T: WhT[b][h][i] = (x @ W)^T, fp16 output (tf32) -----
__global__ __launch_bounds__(256, 2)
void whT_gemm(const float* __restrict__ x, const float* __restrict__ W,
              __half* __restrict__ WhT)
{
    __shared__ uint32_t As[128 * AST];   // [h][d]
    __shared__ uint32_t Bs[128 * AST];   // [i][d]

    const int tid  = threadIdx.x;
    const int warp = tid >> 5, lane = tid & 31;
    const int g = lane >> 2, t = lane & 3;
    const int wm = warp & 1, wn = warp >> 1;
    const int m0 = blockIdx.y * 128;           // h-block
    const int n0 = blockIdx.x * 128;           // global row block

    float acc[4][4][4] = {};

    for (int k0 = 0; k0 < DD; k0 += 32) {
#pragma unroll
        for (int s = 0; s < 4; s++) {
            int f4 = tid + 256 * s;
            int d = f4 >> 5, h4 = f4 & 31;
            float4 v = *(const float4*)(W + (size_t)(k0 + d) * HH + m0 + h4 * 4);
            As[(h4*4 + 0) * AST + d] = f2tf(v.x);
            As[(h4*4 + 1) * AST + d] = f2tf(v.y);
            As[(h4*4 + 2) * AST + d] = f2tf(v.z);
            As[(h4*4 + 3) * AST + d] = f2tf(v.w);
        }
#pragma unroll
        for (int s = 0; s < 4; s++) {
            int f4 = tid + 256 * s;
            int n = f4 >> 3, k4 = f4 & 7;
            float4 v = *(const float4*)(x + (size_t)(n0 + n) * DD + k0 + k4 * 4);
            uint4 u; u.x = f2tf(v.x); u.y = f2tf(v.y); u.z = f2tf(v.z); u.w = f2tf(v.w);
            *(uint4*)&Bs[n * AST + k4 * 4] = u;
        }
        __syncthreads();

#pragma unroll
        for (int ks = 0; ks < 4; ks++) {
            const int kk = ks * 8;
            uint32_t af[4][4], bf[4][2];
#pragma unroll
            for (int mf = 0; mf < 4; mf++) {
                int r0 = wm * 64 + mf * 16 + g;
                af[mf][0] = As[(r0    ) * AST + kk + t];
                af[mf][1] = As[(r0 + 8) * AST + kk + t];
                af[mf][2] = As[(r0    ) * AST + kk + t + 4];
                af[mf][3] = As[(r0 + 8) * AST + kk + t + 4];
            }
#pragma unroll
            for (int nf = 0; nf < 4; nf++) {
                int c0 = wn * 32 + nf * 8 + g;
                bf[nf][0] = Bs[c0 * AST + kk + t];
                bf[nf][1] = Bs[c0 * AST + kk + t + 4];
            }
#pragma unroll
            for (int mf = 0; mf < 4; mf++)
#pragma unroll
                for (int nf = 0; nf < 4; nf++)
                    mma_tf32(acc[mf][nf], af[mf], bf[nf]);
        }
        __syncthreads();
    }

    const int b  = n0 >> 11;
    const int ib = n0 & (NN_ - 1);
#pragma unroll
    for (int mf = 0; mf < 4; mf++) {
        int h = m0 + wm * 64 + mf * 16 + g;
#pragma unroll
        for (int nf = 0; nf < 4; nf++) {
            int i = ib + wn * 32 + nf * 8 + 2 * t;
            __half2 v0 = __floats2half2_rn(acc[mf][nf][0], acc[mf][nf][1]);
            __half2 v1 = __floats2half2_rn(acc[mf][nf][2], acc[mf][nf][3]);
            *(__half2*)(WhT + (size_t)(b * HH + h)     * NN_ + i) = v0;
            *(__half2*)(WhT + (size_t)(b * HH + h + 8) * NN_ + i) = v1;
        }
    }
}

// ---------------- Wh1/Wh2 GEMVs from WhT (fp16) ----------------------------
__global__ __launch_bounds__(256)
void wh12_T(const __half* __restrict__ WhT, const float* __restrict__ a,
            float* __restrict__ Wh1, float* __restrict__ Wh2)
{
    int r = blockIdx.x * 256 + threadIdx.x;
    int b = r >> 11, i = r & (NN_ - 1);
    const __half* base = WhT + (size_t)b * HH * NN_ + i;
    float s1 = 0.f, s2 = 0.f;
#pragma unroll 8
    for (int h = 0; h < HH; h++) {
        float v = __half2float(base[(size_t)h * NN_]);
        s1 += v * a[h];
        s2 += v * a[HH + h];
    }
    Wh1[r] = s1; Wh2[r] = s2;
}

// ---------------- fused: adj -> masked softmax stats + fp16 ws matrix ------
__global__ __launch_bounds__(256)
void pack_stats(const int* __restrict__ adj, const float* __restrict__ Wh1,
                const float* __restrict__ Wh2, __half* __restrict__ ws,
                float* __restrict__ rsum)
{
    const int r = blockIdx.x;
    const int b = r >> 11;
    const int tid = threadIdx.x;
    const float w1 = Wh1[r];
    const float* Wh2b = Wh2 + (b << 11);

    const int4* ap = (const int4*)(adj + (size_t)r * NN_ + tid * 8);
    int4 a0 = ap[0], a1 = ap[1];
    float4 w0 = *(const float4*)(Wh2b + tid * 8);
    float4 w1v = *(const float4*)(Wh2b + tid * 8 + 4);

    int m[8] = { a0.x > 0, a0.y > 0, a0.z > 0, a0.w > 0,
                 a1.x > 0, a1.y > 0, a1.z > 0, a1.w > 0 };
    float wv[8] = { w0.x, w0.y, w0.z, w0.w, w1v.x, w1v.y, w1v.z, w1v.w };

    float lrv[8];
    float mx = -INFINITY;
#pragma unroll
    for (int k = 0; k < 8; k++) {
        float sv = w1 + wv[k];
        float lr = sv > 0.f ? sv : ALPHA * sv;
        lrv[k] = m[k] ? lr : -INFINITY;
        mx = fmaxf(mx, lrv[k]);
    }

    __shared__ float sred[8];
#pragma unroll
    for (int o = 16; o; o >>= 1) mx = fmaxf(mx, __shfl_xor_sync(0xffffffffu, mx, o));
    if ((tid & 31) == 0) sred[tid >> 5] = mx;
    __syncthreads();
    if (tid == 0) {
        float v = sred[0];
#pragma unroll
        for (int w = 1; w < 8; w++) v = fmaxf(v, sred[w]);
        sred[0] = v;
    }
    __syncthreads();
    mx = sred[0];

    float ev[8];
    float sum = 0.f;
#pragma unroll
    for (int k = 0; k < 8; k++) { ev[k] = __expf(lrv[k] - mx); sum += ev[k]; }
    __half2 hq[4];
#pragma unroll
    for (int k = 0; k < 4; k++) hq[k] = __floats2half2_rn(ev[2*k], ev[2*k+1]);
    *(uint4*)(ws + (size_t)r * NN_ + tid * 8) = *(uint4*)hq;

#pragma unroll
    for (int o = 16; o; o >>= 1) sum += __shfl_xor_sync(0xffffffffu, sum, o);
    __syncthreads();
    if ((tid & 31) == 0) sred[tid >> 5] = sum;
    __syncthreads();
    if (tid == 0) {
        float v = 0.f;
#pragma unroll
        for (int w = 0; w < 8; w++) v += sred[w];
        rsum[r] = v;
    }
}

// ---------------- attention GEMM: fp16 MMA, 64i x 128h tiles ---------------
// grid (32 i-tiles, 2 h-tiles, 8 b). k = j in tiles of 64. fp16 output go16.
#define ATTN_SMEM_WORDS (2*128*AST + 2*64*AST + 64)
__global__ __launch_bounds__(256, 3)
void attn_mma(const __half* __restrict__ WhT, const __half* __restrict__ ws,
              const float* __restrict__ rsum, __half* __restrict__ go)
{
    extern __shared__ uint32_t dsm[];
    uint32_t* WhB[2] = { dsm, dsm + 128 * AST };                      // [h][j-half2]
    uint32_t* wsA[2] = { dsm + 2*128*AST, dsm + 2*128*AST + 64*AST }; // [i][j-half2]
    float* fis = (float*)(dsm + 2*128*AST + 2*64*AST);

    const int b = blockIdx.z, i0 = blockIdx.x * 64, h0 = blockIdx.y * 128;
    const int tid = threadIdx.x;
    const int warp = tid >> 5, lane = tid & 31;
    const int g = lane >> 2, t = lane & 3;
    const int wm = warp >> 2, wn = warp & 3;   // 2 i-warps x 4 h-warps

    const __half* WhT_b = WhT + (size_t)(b * HH + h0) * NN_;
    const __half* ws_b  = ws  + (size_t)(b * NN_ + i0) * NN_;

    if (tid < 64) fis[tid] = 1.0f / rsum[b * NN_ + i0 + tid];
    __syncthreads();

    auto issue = [&](int T, int st) {
        const __half* wsrc = WhT_b + T * 64;
#pragma unroll
        for (int s = 0; s < 4; s++) {            // 1024 cp16: 128h x 64j
            int idx = tid + 256 * s;
            int h = idx >> 3, grp = idx & 7;
            cp16(&WhB[st][h * AST + grp * 4], wsrc + (size_t)h * NN_ + grp * 8);
        }
        const __half* asrc = ws_b + T * 64;
#pragma unroll
        for (int s = 0; s < 2; s++) {            // 512 cp16: 64i x 64j
            int idx = tid + 256 * s;
            int i = idx >> 3, grp = idx & 7;
            cp16(&wsA[st][i * AST + grp * 4], asrc + (size_t)i * NN_ + grp * 8);
        }
    };

    float acc[2][4][4] = {};

    issue(0, 0); cp_commit(); cp_wait0(); __syncthreads();

    for (int T = 0; T < NN_ / 64; T++) {
        const int st = T & 1, nst = st ^ 1;
        if (T + 1 < NN_ / 64) issue(T + 1, nst);
        cp_commit();

#pragma unroll
        for (int ks = 0; ks < 4; ks++) {
            const int kk = ks * 8;               // half2-word offset
            uint32_t af[2][4], bf[4][2];
#pragma unroll
            for (int mf = 0; mf < 2; mf++) {
                int r0 = wm * 32 + mf * 16 + g;
                af[mf][0] = wsA[st][(r0    ) * AST + kk + t];
                af[mf][1] = wsA[st][(r0 + 8) * AST + kk + t];
                af[mf][2] = wsA[st][(r0    ) * AST + kk + t + 4];
                af[mf][3] = wsA[st][(r0 + 8) * AST + kk + t + 4];
            }
#pragma unroll
            for (int nf = 0; nf < 4; nf++) {
                int c0 = wn * 32 + nf * 8 + g;
                bf[nf][0] = WhB[st][c0 * AST + kk + t];
                bf[nf][1] = WhB[st][c0 * AST + kk + t + 4];
            }
#pragma unroll
            for (int mf = 0; mf < 2; mf++)
#pragma unroll
                for (int nf = 0; nf < 4; nf++)
                    mma_f16(acc[mf][nf], af[mf], bf[nf]);
        }
        cp_wait0(); __syncthreads();
    }

    // epilogue: fp16 go, row = i
#pragma unroll
    for (int mf = 0; mf < 2; mf++) {
        int il = wm * 32 + mf * 16 + g;
        float s0 = fis[il], s1 = fis[il + 8];
        __half* o0 = go + (size_t)(b * NN_ + i0 + il)     * HH + h0;
        __half* o1 = go + (size_t)(b * NN_ + i0 + il + 8) * HH + h0;
#pragma unroll
        for (int nf = 0; nf < 4; nf++) {
            int hc = wn * 32 + nf * 8 + 2 * t;
            *(__half2*)(o0 + hc) = __floats2half2_rn(acc[mf][nf][0] * s0, acc[mf][nf][1] * s0);
            *(__half2*)(o1 + hc) = __floats2half2_rn(acc[mf][nf][2] * s1, acc[mf][nf][3] * s1);
        }
    }
}

// ---------------- gh GEMM: fp16 MMA, gh16 = x16 @ w_hh16^T + b_hh ----------
__global__ __launch_bounds__(256, 2)
void gh_gemm_f16(const __half* __restrict__ A16, const __half* __restrict__ B16,
                 const float* __restrict__ bias, __half* __restrict__ C16,
                 int N, int K)
{
    __shared__ uint32_t As[128 * AST];
    __shared__ uint32_t Bs[128 * AST];

    const int tid  = threadIdx.x;
    const int warp = tid >> 5, lane = tid & 31;
    const int g = lane >> 2, t = lane & 3;
    const int wm = warp & 1, wn = warp >> 1;   // 2 m x 4 n
    const int m0 = blockIdx.y * 128, n0 = blockIdx.x * 128;

    float acc[4][4][4] = {};

    for (int k0 = 0; k0 < K; k0 += 64) {
#pragma unroll
        for (int s = 0; s < 4; s++) {
            int f4 = tid + 256 * s;
            int m = f4 >> 3, grp = f4 & 7;
            cp16(&As[m * AST + grp * 4], A16 + (size_t)(m0 + m) * K + k0 + grp * 8);
        }
#pragma unroll
        for (int s = 0; s < 4; s++) {
            int f4 = tid + 256 * s;
            int n = f4 >> 3, grp = f4 & 7;
            cp16(&Bs[n * AST + grp * 4], B16 + (size_t)(n0 + n) * K + k0 + grp * 8);
        }
        cp_commit(); cp_wait0(); __syncthreads();

#pragma unroll
        for (int ks = 0; ks < 4; ks++) {
            const int kk = ks * 8;
            uint32_t af[4][4], bf[4][2];
#pragma unroll
            for (int mf = 0; mf < 4; mf++) {
                int r0 = wm * 64 + mf * 16 + g;
                af[mf][0] = As[(r0    ) * AST + kk + t];
                af[mf][1] = As[(r0 + 8) * AST + kk + t];
                af[mf][2] = As[(r0    ) * AST + kk + t + 4];
                af[mf][3] = As[(r0 + 8) * AST + kk + t + 4];
            }
#pragma unroll
            for (int nf = 0; nf < 4; nf++) {
                int c0 = wn * 32 + nf * 8 + g;
                bf[nf][0] = Bs[c0 * AST + kk + t];
                bf[nf][1] = Bs[c0 * AST + kk + t + 4];
            }
#pragma unroll
            for (int mf = 0; mf < 4; mf++)
#pragma unroll
                for (int nf = 0; nf < 4; nf++)
                    mma_f16(acc[mf][nf], af[mf], bf[nf]);
        }
        __syncthreads();
    }

#pragma unroll
    for (int mf = 0; mf < 4; mf++) {
        int row = m0 + wm * 64 + mf * 16 + g;
#pragma unroll
        for (int nf = 0; nf < 4; nf++) {
            int col = n0 + wn * 32 + nf * 8 + 2 * t;
            float b0v = bias[col], b1v = bias[col + 1];
            *(__half2*)(C16 + (size_t)row * N + col) =
                __floats2half2_rn(acc[mf][nf][0] + b0v, acc[mf][nf][1] + b1v);
            *(__half2*)(C16 + (size_t)(row + 8) * N + col) =
                __floats2half2_rn(acc[mf][nf][2] + b0v, acc[mf][nf][3] + b1v);
        }
    }
}

// ---------------- fused gi GEMM (fp16, 3 gates) + GRU epilogue -------------
__global__ __launch_bounds__(256, 2)
void gru_gemm(const __half* __restrict__ go, const __half* __restrict__ wih,
              const float* __restrict__ b_ih, const __half* __restrict__ gh,
              const float* __restrict__ x, float* __restrict__ out)
{
    __shared__ uint32_t As[128 * AST];
    __shared__ uint32_t Bs[3][32 * AST];

    const int tid  = threadIdx.x;
    const int warp = tid >> 5, lane = tid & 31;
    const int g = lane >> 2, t = lane & 3;
    const int wm = warp >> 1, wn = warp & 1;  // 4 m-warps x 2 n-warps
    const int m0 = blockIdx.y * 128;
    const int h0 = blockIdx.x * 32;

    float acc[3][2][2][4] = {};

    for (int k0 = 0; k0 < HH; k0 += 64) {
#pragma unroll
        for (int s = 0; s < 4; s++) {
            int f4 = tid + 256 * s;
            int m = f4 >> 3, grp = f4 & 7;
            cp16(&As[m * AST + grp * 4], go + (size_t)(m0 + m) * HH + k0 + grp * 8);
        }
        // 3 gate tiles, 32n x 64k each: 256 cp16 per gate
        {
            int gate = tid >> 7;                // threads 0..255 cover gates via 2 loops
#pragma unroll
            for (int s = 0; s < 2; s++) {
                int idx = (tid & 127) + 128 * 0;
                int gg = gate + 2 * s;          // gates 0,1 then 2,3(skip)
                if (gg < 3) {
                    int n = (tid & 127) >> 2, grp = (tid & 127) & 3;   // wrong granularity
                }
            }
        }
        // simpler: 768 cp16 total -> 3 per thread
#pragma unroll
        for (int s = 0; s < 3; s++) {
            int idx = tid + 256 * s;            // 0..767
            int gate = idx >> 8;                // 0..2
            int r = idx & 255;
            int n = r >> 3, grp = r & 7;
            cp16(&Bs[gate][n * AST + grp * 4],
                 wih + (size_t)(gate * HH + h0 + n) * HH + k0 + grp * 8);
        }
        cp_commit(); cp_wait0(); __syncthreads();

#pragma unroll
        for (int ks = 0; ks < 4; ks++) {
            const int kk = ks * 8;
            uint32_t af[2][4], bf[3][2][2];
#pragma unroll
            for (int mf = 0; mf < 2; mf++) {
                int r0 = wm * 32 + mf * 16 + g;
                af[mf][0] = As[(r0    ) * AST + kk + t];
                af[mf][1] = As[(r0 + 8) * AST + kk + t];
                af[mf][2] = As[(r0    ) * AST + kk + t + 4];
                af[mf][3] = As[(r0 + 8) * AST + kk + t + 4];
            }
#pragma unroll
            for (int gate = 0; gate < 3; gate++)
#pragma unroll
                for (int nf = 0; nf < 2; nf++) {
                    int c0 = wn * 16 + nf * 8 + g;
                    bf[gate][nf][0] = Bs[gate][c0 * AST + kk + t];
                    bf[gate][nf][1] = Bs[gate][c0 * AST + kk + t + 4];
                }
#pragma unroll
            for (int gate = 0; gate < 3; gate++)
#pragma unroll
                for (int mf = 0; mf < 2; mf++)
#pragma unroll
                    for (int nf = 0; nf < 2; nf++)
                        mma_f16(acc[gate][mf][nf], af[mf], bf[gate][nf]);
        }
        __syncthreads();
    }

    // ---- GRU epilogue
#pragma unroll
    for (int mf = 0; mf < 2; mf++) {
#pragma unroll
        for (int nf = 0; nf < 2; nf++) {
            int col = h0 + wn * 16 + nf * 8 + 2 * t;
            float br0 = b_ih[col],            br1 = b_ih[col + 1];
            float bz0 = b_ih[HH + col],       bz1 = b_ih[HH + col + 1];
            float bn0 = b_ih[2 * HH + col],   bn1 = b_ih[2 * HH + col + 1];
#pragma unroll
            for (int pr = 0; pr < 2; pr++) {
                int row = m0 + wm * 32 + mf * 16 + g + pr * 8;
                const __half* ghr = gh + (size_t)row * (3 * HH);
                __half2 hrh = *(const __half2*)(ghr + col);
                __half2 hzh = *(const __half2*)(ghr + HH + col);
                __half2 hnh = *(const __half2*)(ghr + 2 * HH + col);
                float2 hr = __half22float2(hrh);
                float2 hz = __half22float2(hzh);
                float2 hn = __half22float2(hnh);
                float2 xv = *(const float2*)(x + (size_t)row * HH + col);

                float ir0 = acc[0][mf][nf][pr*2+0] + br0, ir1 = acc[0][mf][nf][pr*2+1] + br1;
                float iz0 = acc[1][mf][nf][pr*2+0] + bz0, iz1 = acc[1][mf][nf][pr*2+1] + bz1;
                float in0 = acc[2][mf][nf][pr*2+0] + bn0, in1 = acc[2][mf][nf][pr*2+1] + bn1;

                float r0g = 1.f / (1.f + __expf(-(ir0 + hr.x)));
                float r1g = 1.f / (1.f + __expf(-(ir1 + hr.y)));
                float z0g = 1.f / (1.f + __expf(-(iz0 + hz.x)));
                float z1g = 1.f / (1.f + __expf(-(iz1 + hz.y)));
                float n0g = tanhf(in0 + r0g * hn.x);
                float n1g = tanhf(in1 + r1g * hn.y);
                float2 o;
                o.x = (1.f - z0g) * n0g + z0g * xv.x;
                o.y = (1.f - z1g) * n1g + z1g * xv.y;
                *(float2*)(out + (size_t)row * HH + col) = o;
            }
        }
    }
}

// ---------------- launch ---------------------------------------------------
extern "C" void kernel_launch(void* const* d_in, const int* in_sizes, int n_in,
                              void* d_out, int out_size)
{
    const int*   adj  = (const int*)  d_in[0];
    const float* x    = (const float*)d_in[1];
    const float* W    = (const float*)d_in[2];
    const float* a    = (const float*)d_in[3];
    const float* w_ih = (const float*)d_in[4];
    const float* w_hh = (const float*)d_in[5];
    const float* b_ih = (const float*)d_in[6];
    const float* b_hh = (const float*)d_in[7];
    float* out = (float*)d_out;

    float *pWh1, *pWh2, *prs;
    __half *pWhT, *pws, *pgo16, *pgh16, *px16, *pwih16, *pwhh16;
    cudaGetSymbolAddress((void**)&pWhT,  g_WhT);
    cudaGetSymbolAddress((void**)&pws,   g_ws);
    cudaGetSymbolAddress((void**)&pgo16, g_go16);
    cudaGetSymbolAddress((void**)&pgh16, g_gh16);
    cudaGetSymbolAddress((void**)&px16,  g_x16);
    cudaGetSymbolAddress((void**)&pwih16, g_wih16);
    cudaGetSymbolAddress((void**)&pwhh16, g_whh16);
    cudaGetSymbolAddress((void**)&pWh1, g_Wh1);
    cudaGetSymbolAddress((void**)&pWh2, g_Wh2);
    cudaGetSymbolAddress((void**)&prs,  g_rs);

    cudaFuncSetAttribute(attn_mma, cudaFuncAttributeMaxDynamicSharedMemorySize,
                         ATTN_SMEM_WORDS * 4);

    // 0) fp16 conversions
    cvt_f16<<<(ROWS * HH) / (256 * 8), 256>>>(x, px16);
    cvt_f16<<<(3 * HH * HH) / (256 * 8), 256>>>(w_ih, pwih16);
    cvt_f16<<<(3 * HH * HH) / (256 * 8), 256>>>(w_hh, pwhh16);

    // 1) WhT = (x @ W)^T  (tf32, fp16 out)
    whT_gemm<<<dim3(ROWS / 128, HH / 128), 256>>>(x, W, pWhT);

    // 2) Wh1/Wh2 GEMVs
    wh12_T<<<ROWS / 256, 256>>>(pWhT, a, pWh1, pWh2);

    // 3) adj -> softmax stats + fp16 ws (single adj pass)
    pack_stats<<<ROWS, 256>>>(adj, pWh1, pWh2, pws, prs);

    // 4) attention GEMM (fp16 MMA) -> go16
    attn_mma<<<dim3(NN_ / 64, HH / 128, BB), 256, ATTN_SMEM_WORDS * 4>>>(
        pWhT, pws, prs, pgo16);

    // 5) gh16 = x16 @ w_hh16^T + b_hh (fp16 MMA)
    gh_gemm_f16<<<dim3(3 * HH / 128, ROWS / 128), 256>>>(px16, pwhh16, b_hh, pgh16, 3 * HH, HH);

    // 6) gi GEMM (fp16, 3 gates) + GRU fused -> out
    gru_gemm<<<dim3(HH / 32, ROWS / 128), 256>>>(pgo16, pwih16, b_ih, pgh16, x, out);
}

// round 6
// speedup vs baseline: 4.0907x; 1.0752x over previous
#include <cuda_runtime.h>
#include <cuda_fp16.h>
#include <cstdint>
#include <math.h>

// Problem constants
#define BB 8
#define NN_ 2048
#define DD 256
#define HH 256
#define ROWS (BB*NN_)          // 16384
#define ALPHA 0.2f

// ---------------- scratch (device globals) ---------------------------------
__device__ __half   g_WhT [(size_t)ROWS*HH];     // fp16 Wh^T [b][h][i]
__device__ __half   g_ws  [(size_t)ROWS*NN_];    // fp16 attention weights [r][j]
__device__ __half   g_go16[(size_t)ROWS*HH];     // fp16 graph_out
__device__ __half   g_gh16[(size_t)ROWS*3*HH];   // fp16 gh
__device__ __half   g_x16 [(size_t)ROWS*HH];     // fp16 x
__device__ __half   g_wih16[3*HH*HH];
__device__ __half   g_whh16[3*HH*HH];
__device__ __half   g_wt16[HH*DD];               // fp16 W^T [h][d]
__device__ float    g_Wh1[ROWS];
__device__ float    g_Wh2[ROWS];
__device__ float    g_rs [ROWS];

// ---------------- helpers ---------------------------------------------------
__device__ __forceinline__ void mma_f16(float* d, const uint32_t* a, const uint32_t* b) {
    asm volatile("mma.sync.aligned.m16n8k16.row.col.f32.f16.f16.f32 "
        "{%0,%1,%2,%3}, {%4,%5,%6,%7}, {%8,%9}, {%0,%1,%2,%3};\n"
        : "+f"(d[0]), "+f"(d[1]), "+f"(d[2]), "+f"(d[3])
        : "r"(a[0]), "r"(a[1]), "r"(a[2]), "r"(a[3]), "r"(b[0]), "r"(b[1]));
}
__device__ __forceinline__ void cp16(void* smem, const void* gmem) {
    uint32_t s = (uint32_t)__cvta_generic_to_shared(smem);
    asm volatile("cp.async.cg.shared.global [%0], [%1], 16;\n" :: "r"(s), "l"(gmem));
}
__device__ __forceinline__ void cp_commit() { asm volatile("cp.async.commit_group;\n" ::: "memory"); }
__device__ __forceinline__ void cp_wait0()  { asm volatile("cp.async.wait_group 0;\n" ::: "memory"); }
__device__ __forceinline__ void cp_wait1()  { asm volatile("cp.async.wait_group 1;\n" ::: "memory"); }

#define AST 36     // [row][k-word] stride: frag LDS bank = (4g+t)%32, conflict-free

// ---------------- elementwise fp32 -> fp16 converter -----------------------
__global__ __launch_bounds__(256)
void cvt_f16(const float* __restrict__ src, __half* __restrict__ dst)
{
    int i = (blockIdx.x * 256 + threadIdx.x) * 8;
    float4 v0 = *(const float4*)(src + i);
    float4 v1 = *(const float4*)(src + i + 4);
    __half2 h[4] = { __floats2half2_rn(v0.x, v0.y), __floats2half2_rn(v0.z, v0.w),
                     __floats2half2_rn(v1.x, v1.y), __floats2half2_rn(v1.z, v1.w) };
    *(uint4*)(dst + i) = *(uint4*)h;
}

// ---------------- W[d][h] -> WT16[h][d] fp16 transpose ---------------------
__global__ void cvt_wT(const float* __restrict__ W, __half* __restrict__ WT)
{
    __shared__ float tle[32][33];
    const int h0 = blockIdx.x * 32, d0 = blockIdx.y * 32;
    const int tx = threadIdx.x, ty = threadIdx.y;    // 32 x 8
#pragma unroll
    for (int k = 0; k < 4; k++)
        tle[ty + 8 * k][tx] = W[(size_t)(d0 + ty + 8 * k) * HH + h0 + tx];
    __syncthreads();
#pragma unroll
    for (int k = 0; k < 4; k++)
        WT[(size_t)(h0 + ty + 8 * k) * DD + d0 + tx] = __float2half(tle[tx][ty + 8 * k]);
}

// ---------------- whT GEMM: WhT[b][h][i] = WT16 @ x16^T (fp16 MMA) ---------
// m = h (256), n = global row (16384), k = d (256). 2-stage cp.async pipeline.
#define WT_SMEM_BYTES (4 * 128 * AST * 4)
__global__ __launch_bounds__(256, 2)
void whT_f16(const __half* __restrict__ WT16, const __half* __restrict__ x16,
             __half* __restrict__ WhT)
{
    extern __shared__ uint32_t dsm[];
    uint32_t* As[2] = { dsm, dsm + 128 * AST };
    uint32_t* Bs[2] = { dsm + 2 * 128 * AST, dsm + 3 * 128 * AST };

    const int tid  = threadIdx.x;
    const int warp = tid >> 5, lane = tid & 31;
    const int g = lane >> 2, t = lane & 3;
    const int wm = warp & 1, wn = warp >> 1;   // 2 m x 4 n
    const int m0 = blockIdx.y * 128;           // h block
    const int n0 = blockIdx.x * 128;           // global row block
    const int b  = n0 >> 11;
    const int ib = n0 & (NN_ - 1);

    auto issue = [&](int T, int st) {
#pragma unroll
        for (int s = 0; s < 4; s++) {
            int f = tid + 256 * s;
            int m = f >> 3, grp = f & 7;
            cp16(&As[st][m * AST + grp * 4], WT16 + (size_t)(m0 + m) * DD + T * 64 + grp * 8);
        }
#pragma unroll
        for (int s = 0; s < 4; s++) {
            int f = tid + 256 * s;
            int n = f >> 3, grp = f & 7;
            cp16(&Bs[st][n * AST + grp * 4], x16 + (size_t)(n0 + n) * DD + T * 64 + grp * 8);
        }
    };

    float acc[4][4][4] = {};

    issue(0, 0); cp_commit();

    for (int T = 0; T < 4; T++) {
        const int st = T & 1;
        if (T + 1 < 4) { issue(T + 1, st ^ 1); cp_commit(); cp_wait1(); }
        else           { cp_wait0(); }
        __syncthreads();

#pragma unroll
        for (int ks = 0; ks < 4; ks++) {
            const int kk = ks * 8;
            uint32_t af[4][4], bf[4][2];
#pragma unroll
            for (int mf = 0; mf < 4; mf++) {
                int r0 = wm * 64 + mf * 16 + g;
                af[mf][0] = As[st][(r0    ) * AST + kk + t];
                af[mf][1] = As[st][(r0 + 8) * AST + kk + t];
                af[mf][2] = As[st][(r0    ) * AST + kk + t + 4];
                af[mf][3] = As[st][(r0 + 8) * AST + kk + t + 4];
            }
#pragma unroll
            for (int nf = 0; nf < 4; nf++) {
                int c0 = wn * 32 + nf * 8 + g;
                bf[nf][0] = Bs[st][c0 * AST + kk + t];
                bf[nf][1] = Bs[st][c0 * AST + kk + t + 4];
            }
#pragma unroll
            for (int mf = 0; mf < 4; mf++)
#pragma unroll
                for (int nf = 0; nf < 4; nf++)
                    mma_f16(acc[mf][nf], af[mf], bf[nf]);
        }
        __syncthreads();
    }

#pragma unroll
    for (int mf = 0; mf < 4; mf++) {
        int h = m0 + wm * 64 + mf * 16 + g;
#pragma unroll
        for (int nf = 0; nf < 4; nf++) {
            int i = ib + wn * 32 + nf * 8 + 2 * t;
            *(__half2*)(WhT + (size_t)(b * HH + h)     * NN_ + i) =
                __floats2half2_rn(acc[mf][nf][0], acc[mf][nf][1]);
            *(__half2*)(WhT + (size_t)(b * HH + h + 8) * NN_ + i) =
                __floats2half2_rn(acc[mf][nf][2], acc[mf][nf][3]);
        }
    }
}

// ---------------- Wh1/Wh2 GEMVs from WhT (fp16) ----------------------------
__global__ __launch_bounds__(256)
void wh12_T(const __half* __restrict__ WhT, const float* __restrict__ a,
            float* __restrict__ Wh1, float* __restrict__ Wh2)
{
    int r = blockIdx.x * 256 + threadIdx.x;
    int b = r >> 11, i = r & (NN_ - 1);
    const __half* base = WhT + (size_t)b * HH * NN_ + i;
    float s1 = 0.f, s2 = 0.f;
#pragma unroll 8
    for (int h = 0; h < HH; h++) {
        float v = __half2float(base[(size_t)h * NN_]);
        s1 += v * a[h];
        s2 += v * a[HH + h];
    }
    Wh1[r] = s1; Wh2[r] = s2;
}

// ---------------- fused: adj -> masked softmax stats + fp16 ws matrix ------
__global__ __launch_bounds__(256)
void pack_stats(const int* __restrict__ adj, const float* __restrict__ Wh1,
                const float* __restrict__ Wh2, __half* __restrict__ ws,
                float* __restrict__ rsum)
{
    const int r = blockIdx.x;
    const int b = r >> 11;
    const int tid = threadIdx.x;
    const float w1 = Wh1[r];
    const float* Wh2b = Wh2 + (b << 11);

    const int4* ap = (const int4*)(adj + (size_t)r * NN_ + tid * 8);
    int4 a0 = ap[0], a1 = ap[1];
    float4 w0 = *(const float4*)(Wh2b + tid * 8);
    float4 w1v = *(const float4*)(Wh2b + tid * 8 + 4);

    int m[8] = { a0.x > 0, a0.y > 0, a0.z > 0, a0.w > 0,
                 a1.x > 0, a1.y > 0, a1.z > 0, a1.w > 0 };
    float wv[8] = { w0.x, w0.y, w0.z, w0.w, w1v.x, w1v.y, w1v.z, w1v.w };

    float lrv[8];
    float mx = -INFINITY;
#pragma unroll
    for (int k = 0; k < 8; k++) {
        float sv = w1 + wv[k];
        float lr = sv > 0.f ? sv : ALPHA * sv;
        lrv[k] = m[k] ? lr : -INFINITY;
        mx = fmaxf(mx, lrv[k]);
    }

    __shared__ float sred[8];
#pragma unroll
    for (int o = 16; o; o >>= 1) mx = fmaxf(mx, __shfl_xor_sync(0xffffffffu, mx, o));
    if ((tid & 31) == 0) sred[tid >> 5] = mx;
    __syncthreads();
    if (tid == 0) {
        float v = sred[0];
#pragma unroll
        for (int w = 1; w < 8; w++) v = fmaxf(v, sred[w]);
        sred[0] = v;
    }
    __syncthreads();
    mx = sred[0];

    float ev[8];
    float sum = 0.f;
#pragma unroll
    for (int k = 0; k < 8; k++) { ev[k] = __expf(lrv[k] - mx); sum += ev[k]; }
    __half2 hq[4];
#pragma unroll
    for (int k = 0; k < 4; k++) hq[k] = __floats2half2_rn(ev[2*k], ev[2*k+1]);
    *(uint4*)(ws + (size_t)r * NN_ + tid * 8) = *(uint4*)hq;

#pragma unroll
    for (int o = 16; o; o >>= 1) sum += __shfl_xor_sync(0xffffffffu, sum, o);
    __syncthreads();
    if ((tid & 31) == 0) sred[tid >> 5] = sum;
    __syncthreads();
    if (tid == 0) {
        float v = 0.f;
#pragma unroll
        for (int w = 0; w < 8; w++) v += sred[w];
        rsum[r] = v;
    }
}

// ---------------- attention GEMM: fp16 MMA, 64i x 128h tiles ---------------
#define ATTN_SMEM_WORDS (2*128*AST + 2*64*AST + 64)
__global__ __launch_bounds__(256, 3)
void attn_mma(const __half* __restrict__ WhT, const __half* __restrict__ ws,
              const float* __restrict__ rsum, __half* __restrict__ go)
{
    extern __shared__ uint32_t dsm[];
    uint32_t* WhB[2] = { dsm, dsm + 128 * AST };
    uint32_t* wsA[2] = { dsm + 2*128*AST, dsm + 2*128*AST + 64*AST };
    float* fis = (float*)(dsm + 2*128*AST + 2*64*AST);

    const int b = blockIdx.z, i0 = blockIdx.x * 64, h0 = blockIdx.y * 128;
    const int tid = threadIdx.x;
    const int warp = tid >> 5, lane = tid & 31;
    const int g = lane >> 2, t = lane & 3;
    const int wm = warp >> 2, wn = warp & 3;   // 2 i-warps x 4 h-warps

    const __half* WhT_b = WhT + (size_t)(b * HH + h0) * NN_;
    const __half* ws_b  = ws  + (size_t)(b * NN_ + i0) * NN_;

    if (tid < 64) fis[tid] = 1.0f / rsum[b * NN_ + i0 + tid];
    __syncthreads();

    auto issue = [&](int T, int st) {
        const __half* wsrc = WhT_b + T * 64;
#pragma unroll
        for (int s = 0; s < 4; s++) {
            int idx = tid + 256 * s;
            int h = idx >> 3, grp = idx & 7;
            cp16(&WhB[st][h * AST + grp * 4], wsrc + (size_t)h * NN_ + grp * 8);
        }
        const __half* asrc = ws_b + T * 64;
#pragma unroll
        for (int s = 0; s < 2; s++) {
            int idx = tid + 256 * s;
            int i = idx >> 3, grp = idx & 7;
            cp16(&wsA[st][i * AST + grp * 4], asrc + (size_t)i * NN_ + grp * 8);
        }
    };

    float acc[2][4][4] = {};

    issue(0, 0); cp_commit(); cp_wait0(); __syncthreads();

    for (int T = 0; T < NN_ / 64; T++) {
        const int st = T & 1, nst = st ^ 1;
        if (T + 1 < NN_ / 64) issue(T + 1, nst);
        cp_commit();

#pragma unroll
        for (int ks = 0; ks < 4; ks++) {
            const int kk = ks * 8;
            uint32_t af[2][4], bf[4][2];
#pragma unroll
            for (int mf = 0; mf < 2; mf++) {
                int r0 = wm * 32 + mf * 16 + g;
                af[mf][0] = wsA[st][(r0    ) * AST + kk + t];
                af[mf][1] = wsA[st][(r0 + 8) * AST + kk + t];
                af[mf][2] = wsA[st][(r0    ) * AST + kk + t + 4];
                af[mf][3] = wsA[st][(r0 + 8) * AST + kk + t + 4];
            }
#pragma unroll
            for (int nf = 0; nf < 4; nf++) {
                int c0 = wn * 32 + nf * 8 + g;
                bf[nf][0] = WhB[st][c0 * AST + kk + t];
                bf[nf][1] = WhB[st][c0 * AST + kk + t + 4];
            }
#pragma unroll
            for (int mf = 0; mf < 2; mf++)
#pragma unroll
                for (int nf = 0; nf < 4; nf++)
                    mma_f16(acc[mf][nf], af[mf], bf[nf]);
        }
        cp_wait0(); __syncthreads();
    }

#pragma unroll
    for (int mf = 0; mf < 2; mf++) {
        int il = wm * 32 + mf * 16 + g;
        float s0 = fis[il], s1 = fis[il + 8];
        __half* o0 = go + (size_t)(b * NN_ + i0 + il)     * HH + h0;
        __half* o1 = go + (size_t)(b * NN_ + i0 + il + 8) * HH + h0;
#pragma unroll
        for (int nf = 0; nf < 4; nf++) {
            int hc = wn * 32 + nf * 8 + 2 * t;
            *(__half2*)(o0 + hc) = __floats2half2_rn(acc[mf][nf][0] * s0, acc[mf][nf][1] * s0);
            *(__half2*)(o1 + hc) = __floats2half2_rn(acc[mf][nf][2] * s1, acc[mf][nf][3] * s1);
        }
    }
}

// ---------------- gh GEMM: fp16 MMA, 2-stage pipeline ----------------------
#define GH_SMEM_BYTES (4 * 128 * AST * 4)
__global__ __launch_bounds__(256, 2)
void gh_gemm_f16(const __half* __restrict__ A16, const __half* __restrict__ B16,
                 const float* __restrict__ bias, __half* __restrict__ C16,
                 int N, int K)
{
    extern __shared__ uint32_t dsm[];
    uint32_t* As[2] = { dsm, dsm + 128 * AST };
    uint32_t* Bs[2] = { dsm + 2 * 128 * AST, dsm + 3 * 128 * AST };

    const int tid  = threadIdx.x;
    const int warp = tid >> 5, lane = tid & 31;
    const int g = lane >> 2, t = lane & 3;
    const int wm = warp & 1, wn = warp >> 1;
    const int m0 = blockIdx.y * 128, n0 = blockIdx.x * 128;
    const int KT = K / 64;

    auto issue = [&](int T, int st) {
#pragma unroll
        for (int s = 0; s < 4; s++) {
            int f = tid + 256 * s;
            int m = f >> 3, grp = f & 7;
            cp16(&As[st][m * AST + grp * 4], A16 + (size_t)(m0 + m) * K + T * 64 + grp * 8);
        }
#pragma unroll
        for (int s = 0; s < 4; s++) {
            int f = tid + 256 * s;
            int n = f >> 3, grp = f & 7;
            cp16(&Bs[st][n * AST + grp * 4], B16 + (size_t)(n0 + n) * K + T * 64 + grp * 8);
        }
    };

    float acc[4][4][4] = {};

    issue(0, 0); cp_commit();

    for (int T = 0; T < KT; T++) {
        const int st = T & 1;
        if (T + 1 < KT) { issue(T + 1, st ^ 1); cp_commit(); cp_wait1(); }
        else            { cp_wait0(); }
        __syncthreads();

#pragma unroll
        for (int ks = 0; ks < 4; ks++) {
            const int kk = ks * 8;
            uint32_t af[4][4], bf[4][2];
#pragma unroll
            for (int mf = 0; mf < 4; mf++) {
                int r0 = wm * 64 + mf * 16 + g;
                af[mf][0] = As[st][(r0    ) * AST + kk + t];
                af[mf][1] = As[st][(r0 + 8) * AST + kk + t];
                af[mf][2] = As[st][(r0    ) * AST + kk + t + 4];
                af[mf][3] = As[st][(r0 + 8) * AST + kk + t + 4];
            }
#pragma unroll
            for (int nf = 0; nf < 4; nf++) {
                int c0 = wn * 32 + nf * 8 + g;
                bf[nf][0] = Bs[st][c0 * AST + kk + t];
                bf[nf][1] = Bs[st][c0 * AST + kk + t + 4];
            }
#pragma unroll
            for (int mf = 0; mf < 4; mf++)
#pragma unroll
                for (int nf = 0; nf < 4; nf++)
                    mma_f16(acc[mf][nf], af[mf], bf[nf]);
        }
        __syncthreads();
    }

#pragma unroll
    for (int mf = 0; mf < 4; mf++) {
        int row = m0 + wm * 64 + mf * 16 + g;
#pragma unroll
        for (int nf = 0; nf < 4; nf++) {
            int col = n0 + wn * 32 + nf * 8 + 2 * t;
            float b0v = bias[col], b1v = bias[col + 1];
            *(__half2*)(C16 + (size_t)row * N + col) =
                __floats2half2_rn(acc[mf][nf][0] + b0v, acc[mf][nf][1] + b1v);
            *(__half2*)(C16 + (size_t)(row + 8) * N + col) =
                __floats2half2_rn(acc[mf][nf][2] + b0v, acc[mf][nf][3] + b1v);
        }
    }
}

// ---------------- fused gi GEMM (fp16, 3 gates) + GRU, 2-stage -------------
#define GRU_SMEM_BYTES ((2*128*AST + 2*3*32*AST) * 4)
__global__ __launch_bounds__(256, 2)
void gru_gemm(const __half* __restrict__ go, const __half* __restrict__ wih,
              const float* __restrict__ b_ih, const __half* __restrict__ gh,
              const float* __restrict__ x, float* __restrict__ out)
{
    extern __shared__ uint32_t dsm[];
    uint32_t* As[2] = { dsm, dsm + 128 * AST };
    uint32_t* Bbase  = dsm + 2 * 128 * AST;   // [st][gate][32*AST]

    const int tid  = threadIdx.x;
    const int warp = tid >> 5, lane = tid & 31;
    const int g = lane >> 2, t = lane & 3;
    const int wm = warp >> 1, wn = warp & 1;  // 4 m-warps x 2 n-warps
    const int m0 = blockIdx.y * 128;
    const int h0 = blockIdx.x * 32;

    auto issue = [&](int T, int st) {
#pragma unroll
        for (int s = 0; s < 4; s++) {
            int f = tid + 256 * s;
            int m = f >> 3, grp = f & 7;
            cp16(&As[st][m * AST + grp * 4], go + (size_t)(m0 + m) * HH + T * 64 + grp * 8);
        }
        uint32_t* Bst = Bbase + st * 3 * 32 * AST;
#pragma unroll
        for (int s = 0; s < 3; s++) {
            int idx = tid + 256 * s;            // 0..767
            int gate = idx >> 8;
            int r = idx & 255;
            int n = r >> 3, grp = r & 7;
            cp16(&Bst[gate * 32 * AST + n * AST + grp * 4],
                 wih + (size_t)(gate * HH + h0 + n) * HH + T * 64 + grp * 8);
        }
    };

    float acc[3][2][2][4] = {};

    issue(0, 0); cp_commit();

    for (int T = 0; T < 4; T++) {
        const int st = T & 1;
        if (T + 1 < 4) { issue(T + 1, st ^ 1); cp_commit(); cp_wait1(); }
        else           { cp_wait0(); }
        __syncthreads();
        uint32_t* Bst = Bbase + st * 3 * 32 * AST;

#pragma unroll
        for (int ks = 0; ks < 4; ks++) {
            const int kk = ks * 8;
            uint32_t af[2][4], bf[3][2][2];
#pragma unroll
            for (int mf = 0; mf < 2; mf++) {
                int r0 = wm * 32 + mf * 16 + g;
                af[mf][0] = As[st][(r0    ) * AST + kk + t];
                af[mf][1] = As[st][(r0 + 8) * AST + kk + t];
                af[mf][2] = As[st][(r0    ) * AST + kk + t + 4];
                af[mf][3] = As[st][(r0 + 8) * AST + kk + t + 4];
            }
#pragma unroll
            for (int gate = 0; gate < 3; gate++)
#pragma unroll
                for (int nf = 0; nf < 2; nf++) {
                    int c0 = wn * 16 + nf * 8 + g;
                    bf[gate][nf][0] = Bst[gate * 32 * AST + c0 * AST + kk + t];
                    bf[gate][nf][1] = Bst[gate * 32 * AST + c0 * AST + kk + t + 4];
                }
#pragma unroll
            for (int gate = 0; gate < 3; gate++)
#pragma unroll
                for (int mf = 0; mf < 2; mf++)
#pragma unroll
                    for (int nf = 0; nf < 2; nf++)
                        mma_f16(acc[gate][mf][nf], af[mf], bf[gate][nf]);
        }
        __syncthreads();
    }

    // ---- GRU epilogue
#pragma unroll
    for (int mf = 0; mf < 2; mf++) {
#pragma unroll
        for (int nf = 0; nf < 2; nf++) {
            int col = h0 + wn * 16 + nf * 8 + 2 * t;
            float br0 = b_ih[col],            br1 = b_ih[col + 1];
            float bz0 = b_ih[HH + col],       bz1 = b_ih[HH + col + 1];
            float bn0 = b_ih[2 * HH + col],   bn1 = b_ih[2 * HH + col + 1];
#pragma unroll
            for (int pr = 0; pr < 2; pr++) {
                int row = m0 + wm * 32 + mf * 16 + g + pr * 8;
                const __half* ghr = gh + (size_t)row * (3 * HH);
                float2 hr = __half22float2(*(const __half2*)(ghr + col));
                float2 hz = __half22float2(*(const __half2*)(ghr + HH + col));
                float2 hn = __half22float2(*(const __half2*)(ghr + 2 * HH + col));
                float2 xv = *(const float2*)(x + (size_t)row * HH + col);

                float ir0 = acc[0][mf][nf][pr*2+0] + br0, ir1 = acc[0][mf][nf][pr*2+1] + br1;
                float iz0 = acc[1][mf][nf][pr*2+0] + bz0, iz1 = acc[1][mf][nf][pr*2+1] + bz1;
                float in0 = acc[2][mf][nf][pr*2+0] + bn0, in1 = acc[2][mf][nf][pr*2+1] + bn1;

                float r0g = 1.f / (1.f + __expf(-(ir0 + hr.x)));
                float r1g = 1.f / (1.f + __expf(-(ir1 + hr.y)));
                float z0g = 1.f / (1.f + __expf(-(iz0 + hz.x)));
                float z1g = 1.f / (1.f + __expf(-(iz1 + hz.y)));
                float n0g = tanhf(in0 + r0g * hn.x);
                float n1g = tanhf(in1 + r1g * hn.y);
                float2 o;
                o.x = (1.f - z0g) * n0g + z0g * xv.x;
                o.y = (1.f - z1g) * n1g + z1g * xv.y;
                *(float2*)(out + (size_t)row * HH + col) = o;
            }
        }
    }
}

// ---------------- launch ---------------------------------------------------
extern "C" void kernel_launch(void* const* d_in, const int* in_sizes, int n_in,
                              void* d_out, int out_size)
{
    const int*   adj  = (const int*)  d_in[0];
    const float* x    = (const float*)d_in[1];
    const float* W    = (const float*)d_in[2];
    const float* a    = (const float*)d_in[3];
    const float* w_ih = (const float*)d_in[4];
    const float* w_hh = (const float*)d_in[5];
    const float* b_ih = (const float*)d_in[6];
    const float* b_hh = (const float*)d_in[7];
    float* out = (float*)d_out;

    float *pWh1, *pWh2, *prs;
    __half *pWhT, *pws, *pgo16, *pgh16, *px16, *pwih16, *pwhh16, *pwt16;
    cudaGetSymbolAddress((void**)&pWhT,  g_WhT);
    cudaGetSymbolAddress((void**)&pws,   g_ws);
    cudaGetSymbolAddress((void**)&pgo16, g_go16);
    cudaGetSymbolAddress((void**)&pgh16, g_gh16);
    cudaGetSymbolAddress((void**)&px16,  g_x16);
    cudaGetSymbolAddress((void**)&pwih16, g_wih16);
    cudaGetSymbolAddress((void**)&pwhh16, g_whh16);
    cudaGetSymbolAddress((void**)&pwt16,  g_wt16);
    cudaGetSymbolAddress((void**)&pWh1, g_Wh1);
    cudaGetSymbolAddress((void**)&pWh2, g_Wh2);
    cudaGetSymbolAddress((void**)&prs,  g_rs);

    cudaFuncSetAttribute(attn_mma, cudaFuncAttributeMaxDynamicSharedMemorySize,
                         ATTN_SMEM_WORDS * 4);
    cudaFuncSetAttribute(whT_f16, cudaFuncAttributeMaxDynamicSharedMemorySize,
                         WT_SMEM_BYTES);
    cudaFuncSetAttribute(gh_gemm_f16, cudaFuncAttributeMaxDynamicSharedMemorySize,
                         GH_SMEM_BYTES);
    cudaFuncSetAttribute(gru_gemm, cudaFuncAttributeMaxDynamicSharedMemorySize,
                         GRU_SMEM_BYTES);

    // 0) fp16 conversions + W transpose
    cvt_f16<<<(ROWS * HH) / (256 * 8), 256>>>(x, px16);
    cvt_f16<<<(3 * HH * HH) / (256 * 8), 256>>>(w_ih, pwih16);
    cvt_f16<<<(3 * HH * HH) / (256 * 8), 256>>>(w_hh, pwhh16);
    cvt_wT<<<dim3(HH / 32, DD / 32), dim3(32, 8)>>>(W, pwt16);

    // 1) WhT = WT16 @ x16^T  (fp16 MMA, 2-stage)
    whT_f16<<<dim3(ROWS / 128, HH / 128), 256, WT_SMEM_BYTES>>>(pwt16, px16, pWhT);

    // 2) Wh1/Wh2 GEMVs
    wh12_T<<<ROWS / 256, 256>>>(pWhT, a, pWh1, pWh2);

    // 3) adj -> softmax stats + fp16 ws (single adj pass)
    pack_stats<<<ROWS, 256>>>(adj, pWh1, pWh2, pws, prs);

    // 4) attention GEMM (fp16 MMA) -> go16
    attn_mma<<<dim3(NN_ / 64, HH / 128, BB), 256, ATTN_SMEM_WORDS * 4>>>(
        pWhT, pws, prs, pgo16);

    // 5) gh16 = x16 @ w_hh16^T + b_hh (fp16 MMA, 2-stage)
    gh_gemm_f16<<<dim3(3 * HH / 128, ROWS / 128), 256, GH_SMEM_BYTES>>>(
        px16, pwhh16, b_hh, pgh16, 3 * HH, HH);

    // 6) gi GEMM (fp16, 3 gates) + GRU fused -> out (2-stage)
    gru_gemm<<<dim3(HH / 32, ROWS / 128), 256, GRU_SMEM_BYTES>>>(
        pgo16, pwih16, b_ih, pgh16, x, out);
}

// round 9
// speedup vs baseline: 4.2500x; 1.0389x over previous
#include <cuda_runtime.h>
#include <cuda_fp16.h>
#include <cstdint>
#include <math.h>

// Problem constants
#define BB 8
#define NN_ 2048
#define DD 256
#define HH 256
#define ROWS (BB*NN_)          // 16384
#define ALPHA 0.2f

// ---------------- scratch (device globals) ---------------------------------
__device__ __half   g_WhT [(size_t)ROWS*HH];     // fp16 Wh^T [b][h][i]
__device__ __half   g_ws  [(size_t)ROWS*NN_];    // fp16 attention weights [r][j]
__device__ __half   g_go16[(size_t)ROWS*HH];     // fp16 graph_out
__device__ __half   g_gh16[(size_t)ROWS*3*HH];   // fp16 gh
__device__ __half   g_x16 [(size_t)ROWS*HH];     // fp16 x
__device__ __half   g_wih16[3*HH*HH];
__device__ __half   g_whh16[3*HH*HH];
__device__ __half   g_wt16[HH*DD];               // fp16 W^T [h][d]
__device__ float    g_Wh1[ROWS];
__device__ float    g_Wh2[ROWS];
__device__ float    g_rs [ROWS];

// ---------------- helpers ---------------------------------------------------
__device__ __forceinline__ void mma_f16(float* d, const uint32_t* a, const uint32_t* b) {
    asm volatile("mma.sync.aligned.m16n8k16.row.col.f32.f16.f16.f32 "
        "{%0,%1,%2,%3}, {%4,%5,%6,%7}, {%8,%9}, {%0,%1,%2,%3};\n"
        : "+f"(d[0]), "+f"(d[1]), "+f"(d[2]), "+f"(d[3])
        : "r"(a[0]), "r"(a[1]), "r"(a[2]), "r"(a[3]), "r"(b[0]), "r"(b[1]));
}
__device__ __forceinline__ void cp16(void* smem, const void* gmem) {
    uint32_t s = (uint32_t)__cvta_generic_to_shared(smem);
    asm volatile("cp.async.cg.shared.global [%0], [%1], 16;\n" :: "r"(s), "l"(gmem));
}
__device__ __forceinline__ void cp_commit() { asm volatile("cp.async.commit_group;\n" ::: "memory"); }
__device__ __forceinline__ void cp_wait0()  { asm volatile("cp.async.wait_group 0;\n" ::: "memory"); }
__device__ __forceinline__ void cp_wait1()  { asm volatile("cp.async.wait_group 1;\n" ::: "memory"); }

#define AST 36     // [row][k-word] stride: frag LDS bank = (4g+t)%32, conflict-free

// ---------------- fused fp32 -> fp16 converter (x, w_ih, w_hh in one) ------
// grid = 2048 (x) + 96 (w_ih) + 96 (w_hh) = 2240 blocks of 256, 8 elems/thread
__global__ __launch_bounds__(256)
void cvt_all(const float* __restrict__ x,  __half* __restrict__ x16,
             const float* __restrict__ wi, __half* __restrict__ wi16,
             const float* __restrict__ wh, __half* __restrict__ wh16)
{
    int bid = blockIdx.x;
    const float* src; __half* dst; int base;
    if (bid < 2048)      { src = x;  dst = x16;  base = bid * 2048; }
    else if (bid < 2144) { src = wi; dst = wi16; base = (bid - 2048) * 2048; }
    else                 { src = wh; dst = wh16; base = (bid - 2144) * 2048; }
    int i = base + threadIdx.x * 8;
    float4 v0 = *(const float4*)(src + i);
    float4 v1 = *(const float4*)(src + i + 4);
    __half2 h[4] = { __floats2half2_rn(v0.x, v0.y), __floats2half2_rn(v0.z, v0.w),
                     __floats2half2_rn(v1.x, v1.y), __floats2half2_rn(v1.z, v1.w) };
    *(uint4*)(dst + i) = *(uint4*)h;
}

// ---------------- W[d][h] -> WT16[h][d] fp16 transpose ---------------------
__global__ void cvt_wT(const float* __restrict__ W, __half* __restrict__ WT)
{
    __shared__ float tle[32][33];
    const int h0 = blockIdx.x * 32, d0 = blockIdx.y * 32;
    const int tx = threadIdx.x, ty = threadIdx.y;    // 32 x 8
#pragma unroll
    for (int k = 0; k < 4; k++)
        tle[ty + 8 * k][tx] = W[(size_t)(d0 + ty + 8 * k) * HH + h0 + tx];
    __syncthreads();
#pragma unroll
    for (int k = 0; k < 4; k++)
        WT[(size_t)(h0 + ty + 8 * k) * DD + d0 + tx] = __float2half(tle[tx][ty + 8 * k]);
}

// ---------------- whT GEMM: WhT[b][h][i] = WT16 @ x16^T (fp16 MMA) ---------
#define WT_SMEM_BYTES (4 * 128 * AST * 4)
__global__ __launch_bounds__(256, 2)
void whT_f16(const __half* __restrict__ WT16, const __half* __restrict__ x16,
             __half* __restrict__ WhT)
{
    extern __shared__ uint32_t dsm[];
    uint32_t* As[2] = { dsm, dsm + 128 * AST };
    uint32_t* Bs[2] = { dsm + 2 * 128 * AST, dsm + 3 * 128 * AST };

    const int tid  = threadIdx.x;
    const int warp = tid >> 5, lane = tid & 31;
    const int g = lane >> 2, t = lane & 3;
    const int wm = warp & 1, wn = warp >> 1;   // 2 m x 4 n
    const int m0 = blockIdx.y * 128;           // h block
    const int n0 = blockIdx.x * 128;           // global row block
    const int b  = n0 >> 11;
    const int ib = n0 & (NN_ - 1);

    auto issue = [&](int T, int st) {
#pragma unroll
        for (int s = 0; s < 4; s++) {
            int f = tid + 256 * s;
            int m = f >> 3, grp = f & 7;
            cp16(&As[st][m * AST + grp * 4], WT16 + (size_t)(m0 + m) * DD + T * 64 + grp * 8);
        }
#pragma unroll
        for (int s = 0; s < 4; s++) {
            int f = tid + 256 * s;
            int n = f >> 3, grp = f & 7;
            cp16(&Bs[st][n * AST + grp * 4], x16 + (size_t)(n0 + n) * DD + T * 64 + grp * 8);
        }
    };

    float acc[4][4][4] = {};

    issue(0, 0); cp_commit();

    for (int T = 0; T < 4; T++) {
        const int st = T & 1;
        if (T + 1 < 4) { issue(T + 1, st ^ 1); cp_commit(); cp_wait1(); }
        else           { cp_wait0(); }
        __syncthreads();

#pragma unroll
        for (int ks = 0; ks < 4; ks++) {
            const int kk = ks * 8;
            uint32_t af[4][4], bf[4][2];
#pragma unroll
            for (int mf = 0; mf < 4; mf++) {
                int r0 = wm * 64 + mf * 16 + g;
                af[mf][0] = As[st][(r0    ) * AST + kk + t];
                af[mf][1] = As[st][(r0 + 8) * AST + kk + t];
                af[mf][2] = As[st][(r0    ) * AST + kk + t + 4];
                af[mf][3] = As[st][(r0 + 8) * AST + kk + t + 4];
            }
#pragma unroll
            for (int nf = 0; nf < 4; nf++) {
                int c0 = wn * 32 + nf * 8 + g;
                bf[nf][0] = Bs[st][c0 * AST + kk + t];
                bf[nf][1] = Bs[st][c0 * AST + kk + t + 4];
            }
#pragma unroll
            for (int mf = 0; mf < 4; mf++)
#pragma unroll
                for (int nf = 0; nf < 4; nf++)
                    mma_f16(acc[mf][nf], af[mf], bf[nf]);
        }
        __syncthreads();
    }

#pragma unroll
    for (int mf = 0; mf < 4; mf++) {
        int h = m0 + wm * 64 + mf * 16 + g;
#pragma unroll
        for (int nf = 0; nf < 4; nf++) {
            int i = ib + wn * 32 + nf * 8 + 2 * t;
            *(__half2*)(WhT + (size_t)(b * HH + h)     * NN_ + i) =
                __floats2half2_rn(acc[mf][nf][0], acc[mf][nf][1]);
            *(__half2*)(WhT + (size_t)(b * HH + h + 8) * NN_ + i) =
                __floats2half2_rn(acc[mf][nf][2], acc[mf][nf][3]);
        }
    }
}

// ---------------- Wh1/Wh2 GEMVs from WhT (fp16) ----------------------------
__global__ __launch_bounds__(256)
void wh12_T(const __half* __restrict__ WhT, const float* __restrict__ a,
            float* __restrict__ Wh1, float* __restrict__ Wh2)
{
    int r = blockIdx.x * 256 + threadIdx.x;
    int b = r >> 11, i = r & (NN_ - 1);
    const __half* base = WhT + (size_t)b * HH * NN_ + i;
    float s1 = 0.f, s2 = 0.f;
#pragma unroll 8
    for (int h = 0; h < HH; h++) {
        float v = __half2float(base[(size_t)h * NN_]);
        s1 += v * a[h];
        s2 += v * a[HH + h];
    }
    Wh1[r] = s1; Wh2[r] = s2;
}

// ---------------- fused: adj -> masked softmax stats + fp16 ws matrix ------
__global__ __launch_bounds__(256)
void pack_stats(const int* __restrict__ adj, const float* __restrict__ Wh1,
                const float* __restrict__ Wh2, __half* __restrict__ ws,
                float* __restrict__ rsum)
{
    const int r = blockIdx.x;
    const int b = r >> 11;
    const int tid = threadIdx.x;
    const float w1 = Wh1[r];
    const float* Wh2b = Wh2 + (b << 11);

    const int4* ap = (const int4*)(adj + (size_t)r * NN_ + tid * 8);
    int4 a0 = ap[0], a1 = ap[1];
    float4 w0 = *(const float4*)(Wh2b + tid * 8);
    float4 w1v = *(const float4*)(Wh2b + tid * 8 + 4);

    int m[8] = { a0.x > 0, a0.y > 0, a0.z > 0, a0.w > 0,
                 a1.x > 0, a1.y > 0, a1.z > 0, a1.w > 0 };
    float wv[8] = { w0.x, w0.y, w0.z, w0.w, w1v.x, w1v.y, w1v.z, w1v.w };

    float lrv[8];
    float mx = -INFINITY;
#pragma unroll
    for (int k = 0; k < 8; k++) {
        float sv = w1 + wv[k];
        float lr = sv > 0.f ? sv : ALPHA * sv;
        lrv[k] = m[k] ? lr : -INFINITY;
        mx = fmaxf(mx, lrv[k]);
    }

    __shared__ float sred[8];
#pragma unroll
    for (int o = 16; o; o >>= 1) mx = fmaxf(mx, __shfl_xor_sync(0xffffffffu, mx, o));
    if ((tid & 31) == 0) sred[tid >> 5] = mx;
    __syncthreads();
    if (tid == 0) {
        float v = sred[0];
#pragma unroll
        for (int w = 1; w < 8; w++) v = fmaxf(v, sred[w]);
        sred[0] = v;
    }
    __syncthreads();
    mx = sred[0];

    float ev[8];
    float sum = 0.f;
#pragma unroll
    for (int k = 0; k < 8; k++) { ev[k] = __expf(lrv[k] - mx); sum += ev[k]; }
    __half2 hq[4];
#pragma unroll
    for (int k = 0; k < 4; k++) hq[k] = __floats2half2_rn(ev[2*k], ev[2*k+1]);
    *(uint4*)(ws + (size_t)r * NN_ + tid * 8) = *(uint4*)hq;

#pragma unroll
    for (int o = 16; o; o >>= 1) sum += __shfl_xor_sync(0xffffffffu, sum, o);
    __syncthreads();
    if ((tid & 31) == 0) sred[tid >> 5] = sum;
    __syncthreads();
    if (tid == 0) {
        float v = 0.f;
#pragma unroll
        for (int w = 0; w < 8; w++) v += sred[w];
        rsum[r] = v;
    }
}

// ---------------- attention GEMM: fp16 MMA, 128i x 128h tiles --------------
// grid (16 i-tiles, 2 h-tiles, 8 b) = 256 blocks, occ 2 -> single wave.
#define ATTN_SMEM_WORDS (4*128*AST + 128)
__global__ __launch_bounds__(256, 2)
void attn_mma(const __half* __restrict__ WhT, const __half* __restrict__ ws,
              const float* __restrict__ rsum, __half* __restrict__ go)
{
    extern __shared__ uint32_t dsm[];
    uint32_t* wsA[2] = { dsm, dsm + 128 * AST };                      // [i][j-half2]
    uint32_t* WhB[2] = { dsm + 2*128*AST, dsm + 3*128*AST };          // [h][j-half2]
    float* fis = (float*)(dsm + 4*128*AST);

    const int b = blockIdx.z, i0 = blockIdx.x * 128, h0 = blockIdx.y * 128;
    const int tid = threadIdx.x;
    const int warp = tid >> 5, lane = tid & 31;
    const int g = lane >> 2, t = lane & 3;
    const int wm = warp >> 2, wn = warp & 3;   // 2 i-warps x 4 h-warps

    const __half* WhT_b = WhT + (size_t)(b * HH + h0) * NN_;
    const __half* ws_b  = ws  + (size_t)(b * NN_ + i0) * NN_;

    if (tid < 128) fis[tid] = 1.0f / rsum[b * NN_ + i0 + tid];
    __syncthreads();

    auto issue = [&](int T, int st) {
        const __half* asrc = ws_b + T * 64;
#pragma unroll
        for (int s = 0; s < 4; s++) {            // 1024 cp16: 128i x 64j
            int idx = tid + 256 * s;
            int i = idx >> 3, grp = idx & 7;
            cp16(&wsA[st][i * AST + grp * 4], asrc + (size_t)i * NN_ + grp * 8);
        }
        const __half* wsrc = WhT_b + T * 64;
#pragma unroll
        for (int s = 0; s < 4; s++) {            // 1024 cp16: 128h x 64j
            int idx = tid + 256 * s;
            int h = idx >> 3, grp = idx & 7;
            cp16(&WhB[st][h * AST + grp * 4], wsrc + (size_t)h * NN_ + grp * 8);
        }
    };

    float acc[4][4][4] = {};

    issue(0, 0); cp_commit(); cp_wait0(); __syncthreads();

    for (int T = 0; T < NN_ / 64; T++) {
        const int st = T & 1, nst = st ^ 1;
        if (T + 1 < NN_ / 64) issue(T + 1, nst);
        cp_commit();

#pragma unroll
        for (int ks = 0; ks < 4; ks++) {
            const int kk = ks * 8;
            uint32_t af[4][4], bf[4][2];
#pragma unroll
            for (int mf = 0; mf < 4; mf++) {
                int r0 = wm * 64 + mf * 16 + g;
                af[mf][0] = wsA[st][(r0    ) * AST + kk + t];
                af[mf][1] = wsA[st][(r0 + 8) * AST + kk + t];
                af[mf][2] = wsA[st][(r0    ) * AST + kk + t + 4];
                af[mf][3] = wsA[st][(r0 + 8) * AST + kk + t + 4];
            }
#pragma unroll
            for (int nf = 0; nf < 4; nf++) {
                int c0 = wn * 32 + nf * 8 + g;
                bf[nf][0] = WhB[st][c0 * AST + kk + t];
                bf[nf][1] = WhB[st][c0 * AST + kk + t + 4];
            }
#pragma unroll
            for (int mf = 0; mf < 4; mf++)
#pragma unroll
                for (int nf = 0; nf < 4; nf++)
                    mma_f16(acc[mf][nf], af[mf], bf[nf]);
        }
        cp_wait0(); __syncthreads();
    }

#pragma unroll
    for (int mf = 0; mf < 4; mf++) {
        int il = wm * 64 + mf * 16 + g;
        float s0 = fis[il], s1 = fis[il + 8];
        __half* o0 = go + (size_t)(b * NN_ + i0 + il)     * HH + h0;
        __half* o1 = go + (size_t)(b * NN_ + i0 + il + 8) * HH + h0;
#pragma unroll
        for (int nf = 0; nf < 4; nf++) {
            int hc = wn * 32 + nf * 8 + 2 * t;
            *(__half2*)(o0 + hc) = __floats2half2_rn(acc[mf][nf][0] * s0, acc[mf][nf][1] * s0);
            *(__half2*)(o1 + hc) = __floats2half2_rn(acc[mf][nf][2] * s1, acc[mf][nf][3] * s1);
        }
    }
}

// ---------------- gh GEMM: fp16 MMA, 128m x 192n tiles, 2-stage ------------
#define GH_SMEM_BYTES (2 * (128 + 192) * AST * 4)
__global__ __launch_bounds__(256, 2)
void gh_gemm_f16(const __half* __restrict__ A16, const __half* __restrict__ B16,
                 const float* __restrict__ bias, __half* __restrict__ C16,
                 int N, int K)
{
    extern __shared__ uint32_t dsm[];
    uint32_t* As[2] = { dsm, dsm + 128 * AST };
    uint32_t* Bs[2] = { dsm + 2 * 128 * AST, dsm + 2 * 128 * AST + 192 * AST };

    const int tid  = threadIdx.x;
    const int warp = tid >> 5, lane = tid & 31;
    const int g = lane >> 2, t = lane & 3;
    const int wm = warp & 1, wn = warp >> 1;   // 2 m x 4 n (48 cols each)
    const int m0 = blockIdx.y * 128, n0 = blockIdx.x * 192;
    const int KT = K / 64;

    auto issue = [&](int T, int st) {
#pragma unroll
        for (int s = 0; s < 4; s++) {
            int f = tid + 256 * s;
            int m = f >> 3, grp = f & 7;
            cp16(&As[st][m * AST + grp * 4], A16 + (size_t)(m0 + m) * K + T * 64 + grp * 8);
        }
#pragma unroll
        for (int s = 0; s < 6; s++) {
            int f = tid + 256 * s;             // 1536 cp16: 192n x 64k
            int n = f >> 3, grp = f & 7;
            cp16(&Bs[st][n * AST + grp * 4], B16 + (size_t)(n0 + n) * K + T * 64 + grp * 8);
        }
    };

    float acc[4][6][4] = {};

    issue(0, 0); cp_commit();

    for (int T = 0; T < KT; T++) {
        const int st = T & 1;
        if (T + 1 < KT) { issue(T + 1, st ^ 1); cp_commit(); cp_wait1(); }
        else            { cp_wait0(); }
        __syncthreads();

#pragma unroll
        for (int ks = 0; ks < 4; ks++) {
            const int kk = ks * 8;
            uint32_t af[4][4], bf[6][2];
#pragma unroll
            for (int mf = 0; mf < 4; mf++) {
                int r0 = wm * 64 + mf * 16 + g;
                af[mf][0] = As[st][(r0    ) * AST + kk + t];
                af[mf][1] = As[st][(r0 + 8) * AST + kk + t];
                af[mf][2] = As[st][(r0    ) * AST + kk + t + 4];
                af[mf][3] = As[st][(r0 + 8) * AST + kk + t + 4];
            }
#pragma unroll
            for (int nf = 0; nf < 6; nf++) {
                int c0 = wn * 48 + nf * 8 + g;
                bf[nf][0] = Bs[st][c0 * AST + kk + t];
                bf[nf][1] = Bs[st][c0 * AST + kk + t + 4];
            }
#pragma unroll
            for (int mf = 0; mf < 4; mf++)
#pragma unroll
                for (int nf = 0; nf < 6; nf++)
                    mma_f16(acc[mf][nf], af[mf], bf[nf]);
        }
        __syncthreads();
    }

#pragma unroll
    for (int mf = 0; mf < 4; mf++) {
        int row = m0 + wm * 64 + mf * 16 + g;
#pragma unroll
        for (int nf = 0; nf < 6; nf++) {
            int col = n0 + wn * 48 + nf * 8 + 2 * t;
            float b0v = bias[col], b1v = bias[col + 1];
            *(__half2*)(C16 + (size_t)row * N + col) =
                __floats2half2_rn(acc[mf][nf][0] + b0v, acc[mf][nf][1] + b1v);
            *(__half2*)(C16 + (size_t)(row + 8) * N + col) =
                __floats2half2_rn(acc[mf][nf][2] + b0v, acc[mf][nf][3] + b1v);
        }
    }
}

// ---------------- fused gi GEMM (fp16, 3 gates) + GRU, 2-stage -------------
#define GRU_SMEM_BYTES ((2*128*AST + 2*3*32*AST) * 4)
__global__ __launch_bounds__(256, 2)
void gru_gemm(const __half* __restrict__ go, const __half* __restrict__ wih,
              const float* __restrict__ b_ih, const __half* __restrict__ gh,
              const float* __restrict__ x, float* __restrict__ out)
{
    extern __shared__ uint32_t dsm[];
    uint32_t* As[2] = { dsm, dsm + 128 * AST };
    uint32_t* Bbase  = dsm + 2 * 128 * AST;   // [st][gate][32*AST]

    const int tid  = threadIdx.x;
    const int warp = tid >> 5, lane = tid & 31;
    const int g = lane >> 2, t = lane & 3;
    const int wm = warp >> 1, wn = warp & 1;  // 4 m-warps x 2 n-warps
    const int m0 = blockIdx.y * 128;
    const int h0 = blockIdx.x * 32;

    auto issue = [&](int T, int st) {
#pragma unroll
        for (int s = 0; s < 4; s++) {
            int f = tid + 256 * s;
            int m = f >> 3, grp = f & 7;
            cp16(&As[st][m * AST + grp * 4], go + (size_t)(m0 + m) * HH + T * 64 + grp * 8);
        }
        uint32_t* Bst = Bbase + st * 3 * 32 * AST;
#pragma unroll
        for (int s = 0; s < 3; s++) {
            int idx = tid + 256 * s;            // 0..767
            int gate = idx >> 8;
            int r = idx & 255;
            int n = r >> 3, grp = r & 7;
            cp16(&Bst[gate * 32 * AST + n * AST + grp * 4],
                 wih + (size_t)(gate * HH + h0 + n) * HH + T * 64 + grp * 8);
        }
    };

    float acc[3][2][2][4] = {};

    issue(0, 0); cp_commit();

    for (int T = 0; T < 4; T++) {
        const int st = T & 1;
        if (T + 1 < 4) { issue(T + 1, st ^ 1); cp_commit(); cp_wait1(); }
        else           { cp_wait0(); }
        __syncthreads();
        uint32_t* Bst = Bbase + st * 3 * 32 * AST;

#pragma unroll
        for (int ks = 0; ks < 4; ks++) {
            const int kk = ks * 8;
            uint32_t af[2][4], bf[3][2][2];
#pragma unroll
            for (int mf = 0; mf < 2; mf++) {
                int r0 = wm * 32 + mf * 16 + g;
                af[mf][0] = As[st][(r0    ) * AST + kk + t];
                af[mf][1] = As[st][(r0 + 8) * AST + kk + t];
                af[mf][2] = As[st][(r0    ) * AST + kk + t + 4];
                af[mf][3] = As[st][(r0 + 8) * AST + kk + t + 4];
            }
#pragma unroll
            for (int gate = 0; gate < 3; gate++)
#pragma unroll
                for (int nf = 0; nf < 2; nf++) {
                    int c0 = wn * 16 + nf * 8 + g;
                    bf[gate][nf][0] = Bst[gate * 32 * AST + c0 * AST + kk + t];
                    bf[gate][nf][1] = Bst[gate * 32 * AST + c0 * AST + kk + t + 4];
                }
#pragma unroll
            for (int gate = 0; gate < 3; gate++)
#pragma unroll
                for (int mf = 0; mf < 2; mf++)
#pragma unroll
                    for (int nf = 0; nf < 2; nf++)
                        mma_f16(acc[gate][mf][nf], af[mf], bf[gate][nf]);
        }
        __syncthreads();
    }

    // ---- GRU epilogue
#pragma unroll
    for (int mf = 0; mf < 2; mf++) {
#pragma unroll
        for (int nf = 0; nf < 2; nf++) {
            int col = h0 + wn * 16 + nf * 8 + 2 * t;
            float br0 = b_ih[col],            br1 = b_ih[col + 1];
            float bz0 = b_ih[HH + col],       bz1 = b_ih[HH + col + 1];
            float bn0 = b_ih[2 * HH + col],   bn1 = b_ih[2 * HH + col + 1];
#pragma unroll
            for (int pr = 0; pr < 2; pr++) {
                int row = m0 + wm * 32 + mf * 16 + g + pr * 8;
                const __half* ghr = gh + (size_t)row * (3 * HH);
                float2 hr = __half22float2(*(const __half2*)(ghr + col));
                float2 hz = __half22float2(*(const __half2*)(ghr + HH + col));
                float2 hn = __half22float2(*(const __half2*)(ghr + 2 * HH + col));
                float2 xv = *(const float2*)(x + (size_t)row * HH + col);

                float ir0 = acc[0][mf][nf][pr*2+0] + br0, ir1 = acc[0][mf][nf][pr*2+1] + br1;
                float iz0 = acc[1][mf][nf][pr*2+0] + bz0, iz1 = acc[1][mf][nf][pr*2+1] + bz1;
                float in0 = acc[2][mf][nf][pr*2+0] + bn0, in1 = acc[2][mf][nf][pr*2+1] + bn1;

                float r0g = 1.f / (1.f + __expf(-(ir0 + hr.x)));
                float r1g = 1.f / (1.f + __expf(-(ir1 + hr.y)));
                float z0g = 1.f / (1.f + __expf(-(iz0 + hz.x)));
                float z1g = 1.f / (1.f + __expf(-(iz1 + hz.y)));
                float n0g = tanhf(in0 + r0g * hn.x);
                float n1g = tanhf(in1 + r1g * hn.y);
                float2 o;
                o.x = (1.f - z0g) * n0g + z0g * xv.x;
                o.y = (1.f - z1g) * n1g + z1g * xv.y;
                *(float2*)(out + (size_t)row * HH + col) = o;
            }
        }
    }
}

// ---------------- launch ---------------------------------------------------
extern "C" void kernel_launch(void* const* d_in, const int* in_sizes, int n_in,
                              void* d_out, int out_size)
{
    const int*   adj  = (const int*)  d_in[0];
    const float* x    = (const float*)d_in[1];
    const float* W    = (const float*)d_in[2];
    const float* a    = (const float*)d_in[3];
    const float* w_ih = (const float*)d_in[4];
    const float* w_hh = (const float*)d_in[5];
    const float* b_ih = (const float*)d_in[6];
    const float* b_hh = (const float*)d_in[7];
    float* out = (float*)d_out;

    float *pWh1, *pWh2, *prs;
    __half *pWhT, *pws, *pgo16, *pgh16, *px16, *pwih16, *pwhh16, *pwt16;
    cudaGetSymbolAddress((void**)&pWhT,  g_WhT);
    cudaGetSymbolAddress((void**)&pws,   g_ws);
    cudaGetSymbolAddress((void**)&pgo16, g_go16);
    cudaGetSymbolAddress((void**)&pgh16, g_gh16);
    cudaGetSymbolAddress((void**)&px16,  g_x16);
    cudaGetSymbolAddress((void**)&pwih16, g_wih16);
    cudaGetSymbolAddress((void**)&pwhh16, g_whh16);
    cudaGetSymbolAddress((void**)&pwt16,  g_wt16);
    cudaGetSymbolAddress((void**)&pWh1, g_Wh1);
    cudaGetSymbolAddress((void**)&pWh2, g_Wh2);
    cudaGetSymbolAddress((void**)&prs,  g_rs);

    cudaFuncSetAttribute(attn_mma, cudaFuncAttributeMaxDynamicSharedMemorySize,
                         ATTN_SMEM_WORDS * 4);
    cudaFuncSetAttribute(whT_f16, cudaFuncAttributeMaxDynamicSharedMemorySize,
                         WT_SMEM_BYTES);
    cudaFuncSetAttribute(gh_gemm_f16, cudaFuncAttributeMaxDynamicSharedMemorySize,
                         GH_SMEM_BYTES);
    cudaFuncSetAttribute(gru_gemm, cudaFuncAttributeMaxDynamicSharedMemorySize,
                         GRU_SMEM_BYTES);

    // 0) fp16 conversions (fused) + W transpose
    cvt_all<<<2240, 256>>>(x, px16, w_ih, pwih16, w_hh, pwhh16);
    cvt_wT<<<dim3(HH / 32, DD / 32), dim3(32, 8)>>>(W, pwt16);

    // 1) WhT = WT16 @ x16^T  (fp16 MMA, 2-stage)
    whT_f16<<<dim3(ROWS / 128, HH / 128), 256, WT_SMEM_BYTES>>>(pwt16, px16, pWhT);

    // 2) Wh1/Wh2 GEMVs
    wh12_T<<<ROWS / 256, 256>>>(pWhT, a, pWh1, pWh2);

    // 3) adj -> softmax stats + fp16 ws (single adj pass)
    pack_stats<<<ROWS, 256>>>(adj, pWh1, pWh2, pws, prs);

    // 4) attention GEMM (fp16 MMA, 128x128 tiles, single wave) -> go16
    attn_mma<<<dim3(NN_ / 128, HH / 128, BB), 256, ATTN_SMEM_WORDS * 4>>>(
        pWhT, pws, prs, pgo16);

    // 5) gh16 = x16 @ w_hh16^T + b_hh (fp16 MMA, 192-wide tiles)
    gh_gemm_f16<<<dim3(3 * HH / 192, ROWS / 128), 256, GH_SMEM_BYTES>>>(
        px16, pwhh16, b_hh, pgh16, 3 * HH, HH);

    // 6) gi GEMM (fp16, 3 gates) + GRU fused -> out (2-stage)
    gru_gemm<<<dim3(HH / 32, ROWS / 128), 256, GRU_SMEM_BYTES>>>(
        pgo16, pwih16, b_ih, pgh16, x, out);
}